// round 1
// baseline (speedup 1.0000x reference)
#include <cuda_runtime.h>
#include <math.h>

// Problem constants
#define BB 16
#define LL 2048
#define DIN 8
#define HH 256
#define NN 64
#define NLAYERS 4
#define GM (BB*LL)      // 32768 rows
#define GK HH           // 256
#define GN (2*HH)       // 512

// Scratch (device globals; no allocation allowed)
__device__ float g_x[(size_t)GM*HH];     // current activations (B,L,H)
__device__ float g_g[(size_t)GM*HH];     // gelu(ssm) output     (B,L,H)
__device__ float g_zz[(size_t)GM*GN];    // GLU pre-activation   (B,L,2H)

// ---------------------------------------------------------------------------
// Encoder: x(B,L,8) @ enc_w^T(8,256) + enc_b -> g_x (B,L,H)
// ---------------------------------------------------------------------------
__global__ void enc_kernel(const float* __restrict__ x,
                           const float* __restrict__ w,
                           const float* __restrict__ b)
{
    int row = blockIdx.x;       // 0..GM-1
    int h = threadIdx.x;        // 0..255
    __shared__ float xr[DIN];
    if (h < DIN) xr[h] = x[row*DIN + h];
    __syncthreads();
    float s = b[h];
    #pragma unroll
    for (int k = 0; k < DIN; k++)
        s = fmaf(xr[k], w[h*DIN + k], s);
    g_x[(size_t)row*HH + h] = s;
}

// ---------------------------------------------------------------------------
// S4D scan: per-channel diagonal SSM recurrence + D-skip + exact gelu.
//   block = 128 threads = 4 warps; covers 16 channels of one batch b.
//   warp handles 4 channels, 8 lanes/channel, 8 complex states/lane.
// Reads g_x (B,L,H) via staged smem tile (coalesced), writes g_g (B,L,H).
// ---------------------------------------------------------------------------
__global__ void __launch_bounds__(128) scan_kernel(
    const float* __restrict__ log_dt,   // + l*H
    const float* __restrict__ logA_re,  // + l*H*N
    const float* __restrict__ A_im,
    const float* __restrict__ C_re,
    const float* __restrict__ C_im,
    const float* __restrict__ Dp)       // + l*H
{
    const int b  = blockIdx.y;
    const int h0 = blockIdx.x * 16;
    const int tid = threadIdx.x;
    const int w = tid >> 5, lane = tid & 31;
    const int cw = lane >> 3;       // channel within warp 0..3
    const int sl = lane & 7;        // state-lane 0..7
    const int cb = w*4 + cw;        // channel within block 0..15
    const int h = h0 + cb;

    float lr[8], li[8], cr[8], ci[8];   // lambda, and (2*C')re / -(2*C')im
    float zr[8], zi[8];

    const float dt = expf(log_dt[h]);
    #pragma unroll
    for (int j = 0; j < 8; j++) {
        int n = sl*8 + j;
        int idx = h*NN + n;
        float are = -expf(logA_re[idx]);
        float aim = A_im[idx];
        float dre = dt*are, dim = dt*aim;
        float er = expf(dre);
        float Lr = er*cosf(dim), Li = er*sinf(dim);
        lr[j] = Lr; li[j] = Li;
        float Cre = C_re[idx], Cim = C_im[idx];
        float nr = Lr - 1.0f, ni = Li;
        float tr = Cre*nr - Cim*ni;
        float ti = Cre*ni + Cim*nr;
        float inv = 2.0f / (are*are + aim*aim);
        cr[j] =  inv*(tr*are + ti*aim);
        ci[j] = -inv*(ti*are - tr*aim);
        zr[j] = 0.f; zi[j] = 0.f;
    }

    __shared__ float u_s[32][17];
    __shared__ float y_s[32][17];
    __shared__ float D_s[16];
    if (tid < 16) D_s[tid] = Dp[h0 + tid];

    const float* xb = g_x + (size_t)b*LL*HH + h0;
    float*       gb = g_g + (size_t)b*LL*HH + h0;

    for (int tc = 0; tc < LL/32; tc++) {
        __syncthreads();                       // protect u_s/y_s reuse
        #pragma unroll
        for (int i = 0; i < 4; i++) {
            int e = tid + i*128;
            int tt = e >> 4, hh = e & 15;
            u_s[tt][hh] = xb[(size_t)(tc*32 + tt)*HH + hh];
        }
        __syncthreads();

        #pragma unroll 4
        for (int j = 0; j < 32; j++) {
            float u = u_s[j][cb];
            float p = 0.f;
            #pragma unroll
            for (int q = 0; q < 8; q++) {
                float t1  = fmaf(lr[q], zr[q], u);
                float nzr = fmaf(-li[q], zi[q], t1);
                float t2  = li[q]*zr[q];
                float nzi = fmaf(lr[q], zi[q], t2);
                zr[q] = nzr; zi[q] = nzi;
                p = fmaf(cr[q], nzr, p);
                p = fmaf(ci[q], nzi, p);
            }
            p += __shfl_xor_sync(0xffffffffu, p, 4);
            p += __shfl_xor_sync(0xffffffffu, p, 2);
            p += __shfl_xor_sync(0xffffffffu, p, 1);
            if (sl == 0) y_s[j][cb] = p;
        }
        __syncthreads();

        #pragma unroll
        for (int i = 0; i < 4; i++) {
            int e = tid + i*128;
            int tt = e >> 4, hh = e & 15;
            float uu = u_s[tt][hh];
            float yv = fmaf(D_s[hh], uu, y_s[tt][hh]);
            float gv = 0.5f*yv*(1.0f + erff(yv*0.70710678118654752f));
            gb[(size_t)(tc*32 + tt)*HH + hh] = gv;
        }
    }
}

// ---------------------------------------------------------------------------
// SGEMM: g_zz = g_g (32768x256) @ W^T (256x512) + bias.  64x64 tiles, 4x4 micro.
// ---------------------------------------------------------------------------
__global__ void __launch_bounds__(256) gemm_kernel(
    const float* __restrict__ Wt,     // + l*GN*GK, layout (GN, GK)
    const float* __restrict__ bias)   // + l*GN
{
    __shared__ float As[16][68];
    __shared__ float Bs[16][68];
    const int m0 = blockIdx.y << 6;
    const int n0 = blockIdx.x << 6;
    const int tid = threadIdx.x;
    const int tm = tid >> 4, tn = tid & 15;
    const int lr = tid >> 2, lq = tid & 3;

    float acc[4][4];
    #pragma unroll
    for (int i = 0; i < 4; i++)
        #pragma unroll
        for (int j = 0; j < 4; j++) acc[i][j] = 0.f;

    const float* Aptr = g_g + (size_t)(m0 + lr)*GK + lq*4;
    const float* Bptr = Wt  + (size_t)(n0 + lr)*GK + lq*4;

    for (int k0 = 0; k0 < GK; k0 += 16) {
        float4 av = *(const float4*)(Aptr + k0);
        float4 bv = *(const float4*)(Bptr + k0);
        __syncthreads();
        As[lq*4+0][lr] = av.x; As[lq*4+1][lr] = av.y;
        As[lq*4+2][lr] = av.z; As[lq*4+3][lr] = av.w;
        Bs[lq*4+0][lr] = bv.x; Bs[lq*4+1][lr] = bv.y;
        Bs[lq*4+2][lr] = bv.z; Bs[lq*4+3][lr] = bv.w;
        __syncthreads();
        #pragma unroll
        for (int k = 0; k < 16; k++) {
            float4 a  = *(const float4*)&As[k][tm << 2];
            float4 bb = *(const float4*)&Bs[k][tn << 2];
            acc[0][0]=fmaf(a.x,bb.x,acc[0][0]); acc[0][1]=fmaf(a.x,bb.y,acc[0][1]);
            acc[0][2]=fmaf(a.x,bb.z,acc[0][2]); acc[0][3]=fmaf(a.x,bb.w,acc[0][3]);
            acc[1][0]=fmaf(a.y,bb.x,acc[1][0]); acc[1][1]=fmaf(a.y,bb.y,acc[1][1]);
            acc[1][2]=fmaf(a.y,bb.z,acc[1][2]); acc[1][3]=fmaf(a.y,bb.w,acc[1][3]);
            acc[2][0]=fmaf(a.z,bb.x,acc[2][0]); acc[2][1]=fmaf(a.z,bb.y,acc[2][1]);
            acc[2][2]=fmaf(a.z,bb.z,acc[2][2]); acc[2][3]=fmaf(a.z,bb.w,acc[2][3]);
            acc[3][0]=fmaf(a.w,bb.x,acc[3][0]); acc[3][1]=fmaf(a.w,bb.y,acc[3][1]);
            acc[3][2]=fmaf(a.w,bb.z,acc[3][2]); acc[3][3]=fmaf(a.w,bb.w,acc[3][3]);
        }
    }

    float b0 = bias[n0 + tn*4 + 0];
    float b1 = bias[n0 + tn*4 + 1];
    float b2 = bias[n0 + tn*4 + 2];
    float b3 = bias[n0 + tn*4 + 3];
    #pragma unroll
    for (int i = 0; i < 4; i++) {
        size_t mm = (size_t)(m0 + tm*4 + i);
        float4 o;
        o.x = acc[i][0] + b0; o.y = acc[i][1] + b1;
        o.z = acc[i][2] + b2; o.w = acc[i][3] + b3;
        *(float4*)(g_zz + mm*GN + n0 + tn*4) = o;
    }
}

// ---------------------------------------------------------------------------
// GLU + residual + LayerNorm (in-place update of g_x). One block per row.
// ---------------------------------------------------------------------------
__global__ void __launch_bounds__(256) glu_ln_kernel(
    const float* __restrict__ lng,    // + l*H
    const float* __restrict__ lnb)
{
    const int row = blockIdx.x;
    const int j = threadIdx.x;
    const size_t zb = (size_t)row*GN;
    float a  = g_zz[zb + j];
    float b2 = g_zz[zb + HH + j];
    float q  = a * (1.0f / (1.0f + expf(-b2)));
    float s  = q + g_x[(size_t)row*HH + j];

    float v1 = s, v2 = s*s;
    #pragma unroll
    for (int o = 16; o > 0; o >>= 1) {
        v1 += __shfl_xor_sync(0xffffffffu, v1, o);
        v2 += __shfl_xor_sync(0xffffffffu, v2, o);
    }
    __shared__ float r1[8], r2[8];
    int w = j >> 5, ln = j & 31;
    if (ln == 0) { r1[w] = v1; r2[w] = v2; }
    __syncthreads();
    float sum = 0.f, sq = 0.f;
    #pragma unroll
    for (int i = 0; i < 8; i++) { sum += r1[i]; sq += r2[i]; }
    float mean = sum * (1.0f/HH);
    float var  = sq * (1.0f/HH) - mean*mean;
    float inv  = rsqrtf(var + 1e-5f);
    g_x[(size_t)row*HH + j] = (s - mean)*inv*lng[j] + lnb[j];
}

// ---------------------------------------------------------------------------
// Heads: mu/alpha = softplus(x . w + b). One warp per row.
// ---------------------------------------------------------------------------
__device__ __forceinline__ float softplus_f(float x) {
    return fmaxf(x, 0.f) + log1pf(expf(-fabsf(x)));
}

__global__ void __launch_bounds__(256) head_kernel(
    const float* __restrict__ mu_w, const float* __restrict__ mu_b,
    const float* __restrict__ al_w, const float* __restrict__ al_b,
    float* __restrict__ out, int half)
{
    const int w = threadIdx.x >> 5, ln = threadIdx.x & 31;
    const int row = blockIdx.x*8 + w;
    const float* xr = g_x + (size_t)row*HH;
    float sm = 0.f, sa = 0.f;
    #pragma unroll
    for (int i = 0; i < 8; i++) {
        float v = xr[ln + i*32];
        sm = fmaf(v, mu_w[ln + i*32], sm);
        sa = fmaf(v, al_w[ln + i*32], sa);
    }
    #pragma unroll
    for (int o = 16; o > 0; o >>= 1) {
        sm += __shfl_xor_sync(0xffffffffu, sm, o);
        sa += __shfl_xor_sync(0xffffffffu, sa, o);
    }
    if (ln == 0) {
        out[row]        = softplus_f(sm + mu_b[0]);
        out[half + row] = softplus_f(sa + al_b[0]);
    }
}

// ---------------------------------------------------------------------------
extern "C" void kernel_launch(void* const* d_in, const int* in_sizes, int n_in,
                              void* d_out, int out_size)
{
    const float* x      = (const float*)d_in[0];
    const float* enc_w  = (const float*)d_in[1];
    const float* enc_b  = (const float*)d_in[2];
    const float* log_dt = (const float*)d_in[3];
    const float* logA   = (const float*)d_in[4];
    const float* A_im   = (const float*)d_in[5];
    const float* C_re   = (const float*)d_in[6];
    const float* C_im   = (const float*)d_in[7];
    const float* Dp     = (const float*)d_in[8];
    const float* out_w  = (const float*)d_in[9];
    const float* out_b  = (const float*)d_in[10];
    const float* ln_g   = (const float*)d_in[11];
    const float* ln_b   = (const float*)d_in[12];
    const float* mu_w   = (const float*)d_in[13];
    const float* mu_b   = (const float*)d_in[14];
    const float* al_w   = (const float*)d_in[15];
    const float* al_b   = (const float*)d_in[16];
    float* out = (float*)d_out;

    enc_kernel<<<GM, HH>>>(x, enc_w, enc_b);

    for (int l = 0; l < NLAYERS; l++) {
        scan_kernel<<<dim3(HH/16, BB), 128>>>(
            log_dt + l*HH,
            logA   + (size_t)l*HH*NN,
            A_im   + (size_t)l*HH*NN,
            C_re   + (size_t)l*HH*NN,
            C_im   + (size_t)l*HH*NN,
            Dp     + l*HH);
        gemm_kernel<<<dim3(GN/64, GM/64), 256>>>(
            out_w + (size_t)l*GN*GK,
            out_b + (size_t)l*GN);
        glu_ln_kernel<<<GM, HH>>>(ln_g + l*HH, ln_b + l*HH);
    }

    head_kernel<<<GM/8, 256>>>(mu_w, mu_b, al_w, al_b, out, out_size/2);
}

// round 2
// speedup vs baseline: 1.1650x; 1.1650x over previous
#include <cuda_runtime.h>
#include <math.h>

// Problem constants
#define BB 16
#define LL 2048
#define DIN 8
#define HH 256
#define NN 64
#define NLAYERS 4
#define GM (BB*LL)      // 32768 rows
#define GK HH           // 256
#define GN (2*HH)       // 512

typedef unsigned long long ull;

// Scratch (device globals; no allocation allowed)
__device__ float g_x[(size_t)GM*HH];     // current activations (B,L,H)
__device__ float g_g[(size_t)GM*HH];     // gelu(ssm) output     (B,L,H)
__device__ float g_s[(size_t)GM*HH];     // GLU+residual (pre-LN) (B,L,H)

// ---------------------------------------------------------------------------
// packed f32x2 helpers (Blackwell sm_100+)
// ---------------------------------------------------------------------------
__device__ __forceinline__ ull f2_fma(ull a, ull b, ull c) {
    ull d; asm("fma.rn.f32x2 %0,%1,%2,%3;" : "=l"(d) : "l"(a), "l"(b), "l"(c)); return d;
}
__device__ __forceinline__ ull f2_mul(ull a, ull b) {
    ull d; asm("mul.rn.f32x2 %0,%1,%2;" : "=l"(d) : "l"(a), "l"(b)); return d;
}
__device__ __forceinline__ ull f2_pack(float lo, float hi) {
    ull d; asm("mov.b64 %0,{%1,%2};" : "=l"(d) : "f"(lo), "f"(hi)); return d;
}
__device__ __forceinline__ float f2_sum(ull v) {
    float lo, hi; asm("mov.b64 {%0,%1},%2;" : "=f"(lo), "=f"(hi) : "l"(v)); return lo + hi;
}

// ---------------------------------------------------------------------------
// Encoder: x(B,L,8) @ enc_w^T + enc_b -> g_x (B,L,H)
// ---------------------------------------------------------------------------
__global__ void enc_kernel(const float* __restrict__ x,
                           const float* __restrict__ w,
                           const float* __restrict__ b)
{
    int row = blockIdx.x;
    int h = threadIdx.x;
    __shared__ float xr[DIN];
    if (h < DIN) xr[h] = x[row*DIN + h];
    __syncthreads();
    float s = b[h];
    #pragma unroll
    for (int k = 0; k < DIN; k++)
        s = fmaf(xr[k], w[h*DIN + k], s);
    g_x[(size_t)row*HH + h] = s;
}

// ---------------------------------------------------------------------------
// S4D scan with packed f32x2 state updates.
//   block = 128 threads = 4 warps; 16 channels of one batch.
//   warp: 4 channels x 8 lanes/channel; each lane: 8 complex states = 4 pairs.
// ---------------------------------------------------------------------------
__global__ void __launch_bounds__(128) scan_kernel(
    const float* __restrict__ log_dt,
    const float* __restrict__ logA_re,
    const float* __restrict__ A_im,
    const float* __restrict__ C_re,
    const float* __restrict__ C_im,
    const float* __restrict__ Dp)
{
    const int b  = blockIdx.y;
    const int h0 = blockIdx.x * 16;
    const int tid = threadIdx.x;
    const int w = tid >> 5, lane = tid & 31;
    const int cw = lane >> 3;
    const int sl = lane & 7;
    const int cb = w*4 + cw;
    const int h = h0 + cb;

    // scalar precompute
    float lr[8], li[8], cr[8], ci[8];
    const float dt = expf(log_dt[h]);
    #pragma unroll
    for (int j = 0; j < 8; j++) {
        int n = sl*8 + j;
        int idx = h*NN + n;
        float are = -expf(logA_re[idx]);
        float aim = A_im[idx];
        float dre = dt*are, dim = dt*aim;
        float er = expf(dre);
        float Lr = er*cosf(dim), Li = er*sinf(dim);
        lr[j] = Lr; li[j] = Li;
        float Cre = C_re[idx], Cim = C_im[idx];
        float nr = Lr - 1.0f, ni = Li;
        float tr = Cre*nr - Cim*ni;
        float ti = Cre*ni + Cim*nr;
        float inv = 2.0f / (are*are + aim*aim);
        cr[j] =  inv*(tr*are + ti*aim);
        ci[j] = -inv*(ti*are - tr*aim);
    }

    // pack state pairs (2q, 2q+1)
    ull lr2[4], li2[4], nli2[4], cr2[4], ci2[4], zr2[4], zi2[4];
    #pragma unroll
    for (int q = 0; q < 4; q++) {
        lr2[q]  = f2_pack(lr[2*q],  lr[2*q+1]);
        li2[q]  = f2_pack(li[2*q],  li[2*q+1]);
        nli2[q] = f2_pack(-li[2*q], -li[2*q+1]);
        cr2[q]  = f2_pack(cr[2*q],  cr[2*q+1]);
        ci2[q]  = f2_pack(ci[2*q],  ci[2*q+1]);
        zr2[q]  = 0ull;
        zi2[q]  = 0ull;
    }

    __shared__ float u_s[32][17];
    __shared__ float y_s[32][17];
    __shared__ float D_s[16];
    if (tid < 16) D_s[tid] = Dp[h0 + tid];

    const float* xb = g_x + (size_t)b*LL*HH + h0;
    float*       gb = g_g + (size_t)b*LL*HH + h0;

    for (int tc = 0; tc < LL/32; tc++) {
        __syncthreads();
        #pragma unroll
        for (int i = 0; i < 4; i++) {
            int e = tid + i*128;
            int tt = e >> 4, hh = e & 15;
            u_s[tt][hh] = xb[(size_t)(tc*32 + tt)*HH + hh];
        }
        __syncthreads();

        #pragma unroll 4
        for (int j = 0; j < 32; j++) {
            float u = u_s[j][cb];
            ull u2 = f2_pack(u, u);
            ull p2;
            // q = 0 (init p2 with mul)
            {
                ull t = f2_fma(lr2[0], zr2[0], u2);
                t = f2_fma(nli2[0], zi2[0], t);
                ull s = f2_mul(li2[0], zr2[0]);
                s = f2_fma(lr2[0], zi2[0], s);
                zr2[0] = t; zi2[0] = s;
                p2 = f2_mul(cr2[0], t);
                p2 = f2_fma(ci2[0], s, p2);
            }
            #pragma unroll
            for (int q = 1; q < 4; q++) {
                ull t = f2_fma(lr2[q], zr2[q], u2);
                t = f2_fma(nli2[q], zi2[q], t);
                ull s = f2_mul(li2[q], zr2[q]);
                s = f2_fma(lr2[q], zi2[q], s);
                zr2[q] = t; zi2[q] = s;
                p2 = f2_fma(cr2[q], t, p2);
                p2 = f2_fma(ci2[q], s, p2);
            }
            float p = f2_sum(p2);
            p += __shfl_xor_sync(0xffffffffu, p, 4);
            p += __shfl_xor_sync(0xffffffffu, p, 2);
            p += __shfl_xor_sync(0xffffffffu, p, 1);
            if (sl == 0) y_s[j][cb] = p;
        }
        __syncthreads();

        #pragma unroll
        for (int i = 0; i < 4; i++) {
            int e = tid + i*128;
            int tt = e >> 4, hh = e & 15;
            float uu = u_s[tt][hh];
            float yv = fmaf(D_s[hh], uu, y_s[tt][hh]);
            float gv = 0.5f*yv*(1.0f + erff(yv*0.70710678118654752f));
            gb[(size_t)(tc*32 + tt)*HH + hh] = gv;
        }
    }
}

// ---------------------------------------------------------------------------
// 3xTF32 tensor-core GEMM with fused GLU + bias + residual epilogue.
//   Computes zz = g_g(32768x256) @ W^T(256x512) + b, then
//   s = zz[:, :256] * sigmoid(zz[:, 256:]) + g_x, written to g_s.
//   Column pairing: block tile col c -> W row nb*64 + (c>>1) + (c&1)*256,
//   so (left,right) of a GLU pair land in the SAME thread's (even,odd)
//   accumulator registers of the m16n8k8 fragment.
// ---------------------------------------------------------------------------
__device__ __forceinline__ unsigned tf32_cvt(float f) {
    unsigned r; asm("cvt.rna.tf32.f32 %0,%1;" : "=r"(r) : "f"(f)); return r;
}
__device__ __forceinline__ float2 tf32_split(float v) {
    unsigned hb = tf32_cvt(v);
    float hf = __uint_as_float(hb);
    unsigned lb = tf32_cvt(v - hf);
    return make_float2(hf, __uint_as_float(lb));
}
__device__ __forceinline__ void mma_tf32(float* d, const unsigned* a, const unsigned* b) {
    asm volatile(
        "mma.sync.aligned.m16n8k8.row.col.f32.tf32.tf32.f32 "
        "{%0,%1,%2,%3},{%4,%5,%6,%7},{%8,%9},{%0,%1,%2,%3};"
        : "+f"(d[0]), "+f"(d[1]), "+f"(d[2]), "+f"(d[3])
        : "r"(a[0]), "r"(a[1]), "r"(a[2]), "r"(a[3]), "r"(b[0]), "r"(b[1]));
}

__global__ void __launch_bounds__(256) gemm_glu_kernel(
    const float* __restrict__ Wt,     // + l*GN*GK, (GN, GK)
    const float* __restrict__ bias)   // + l*GN
{
    __shared__ float2 Ash[128][20];   // {hi,lo} tf32 pairs, k-chunk 16 + pad 4
    __shared__ float2 Bsh[128][20];

    const int m0  = blockIdx.y * 128;
    const int nb  = blockIdx.x;       // 0..3
    const int tid = threadIdx.x;
    const int lane = tid & 31, w = tid >> 5;
    const int wm = w & 1;             // m half (64 rows)
    const int wn = w >> 1;            // n quarter (32 cols)
    const int lr = lane >> 2, lc = lane & 3;

    float acc[4][4][4];
    #pragma unroll
    for (int mi = 0; mi < 4; mi++)
        #pragma unroll
        for (int ni = 0; ni < 4; ni++)
            #pragma unroll
            for (int r = 0; r < 4; r++) acc[mi][ni][r] = 0.f;

    const int ldr = tid >> 2;         // 0..63
    const int ldk = (tid & 3) * 4;

    for (int kc = 0; kc < 16; kc++) {
        const int k0 = kc * 16;
        __syncthreads();
        #pragma unroll
        for (int i = 0; i < 2; i++) {
            int r = ldr + i*64;
            float4 av = *(const float4*)(g_g + (size_t)(m0 + r)*GK + k0 + ldk);
            Ash[r][ldk+0] = tf32_split(av.x);
            Ash[r][ldk+1] = tf32_split(av.y);
            Ash[r][ldk+2] = tf32_split(av.z);
            Ash[r][ldk+3] = tf32_split(av.w);
            int wr = nb*64 + (r >> 1) + (r & 1)*256;
            float4 bv = *(const float4*)(Wt + (size_t)wr*GK + k0 + ldk);
            Bsh[r][ldk+0] = tf32_split(bv.x);
            Bsh[r][ldk+1] = tf32_split(bv.y);
            Bsh[r][ldk+2] = tf32_split(bv.z);
            Bsh[r][ldk+3] = tf32_split(bv.w);
        }
        __syncthreads();

        #pragma unroll
        for (int ks = 0; ks < 2; ks++) {
            const int kk = ks*8 + lc;
            unsigned ah[4][4], al[4][4];
            #pragma unroll
            for (int mi = 0; mi < 4; mi++) {
                int rr = wm*64 + mi*16 + lr;
                float2 v0 = Ash[rr  ][kk];
                float2 v1 = Ash[rr+8][kk];
                float2 v2 = Ash[rr  ][kk+4];
                float2 v3 = Ash[rr+8][kk+4];
                ah[mi][0] = __float_as_uint(v0.x); al[mi][0] = __float_as_uint(v0.y);
                ah[mi][1] = __float_as_uint(v1.x); al[mi][1] = __float_as_uint(v1.y);
                ah[mi][2] = __float_as_uint(v2.x); al[mi][2] = __float_as_uint(v2.y);
                ah[mi][3] = __float_as_uint(v3.x); al[mi][3] = __float_as_uint(v3.y);
            }
            unsigned bh[4][2], bl[4][2];
            #pragma unroll
            for (int ni = 0; ni < 4; ni++) {
                int cc = wn*32 + ni*8 + lr;
                float2 u0 = Bsh[cc][kk];
                float2 u1 = Bsh[cc][kk+4];
                bh[ni][0] = __float_as_uint(u0.x); bl[ni][0] = __float_as_uint(u0.y);
                bh[ni][1] = __float_as_uint(u1.x); bl[ni][1] = __float_as_uint(u1.y);
            }
            #pragma unroll
            for (int mi = 0; mi < 4; mi++)
                #pragma unroll
                for (int ni = 0; ni < 4; ni++) {
                    mma_tf32(acc[mi][ni], ah[mi], bh[ni]);
                    mma_tf32(acc[mi][ni], ah[mi], bl[ni]);
                    mma_tf32(acc[mi][ni], al[mi], bh[ni]);
                }
        }
    }

    // Epilogue: GLU + bias + residual, write g_s.
    #pragma unroll
    for (int ni = 0; ni < 4; ni++) {
        const int oc = nb*64 + wn*16 + ni*4 + lc;   // 0..255
        const float bL = bias[oc];
        const float bR = bias[oc + 256];
        #pragma unroll
        for (int mi = 0; mi < 4; mi++) {
            int mg = m0 + wm*64 + mi*16 + lr;
            {
                float zl = acc[mi][ni][0] + bL;
                float zr_ = acc[mi][ni][1] + bR;
                float sv = zl * (1.0f/(1.0f + expf(-zr_))) + g_x[(size_t)mg*HH + oc];
                g_s[(size_t)mg*HH + oc] = sv;
            }
            {
                int mg2 = mg + 8;
                float zl = acc[mi][ni][2] + bL;
                float zr_ = acc[mi][ni][3] + bR;
                float sv = zl * (1.0f/(1.0f + expf(-zr_))) + g_x[(size_t)mg2*HH + oc];
                g_s[(size_t)mg2*HH + oc] = sv;
            }
        }
    }
}

// ---------------------------------------------------------------------------
// LayerNorm: g_x = LN(g_s). One block per row.
// ---------------------------------------------------------------------------
__global__ void __launch_bounds__(256) ln_kernel(
    const float* __restrict__ lng,
    const float* __restrict__ lnb)
{
    const int row = blockIdx.x;
    const int j = threadIdx.x;
    float s = g_s[(size_t)row*HH + j];

    float v1 = s, v2 = s*s;
    #pragma unroll
    for (int o = 16; o > 0; o >>= 1) {
        v1 += __shfl_xor_sync(0xffffffffu, v1, o);
        v2 += __shfl_xor_sync(0xffffffffu, v2, o);
    }
    __shared__ float r1[8], r2[8];
    int w = j >> 5, ln = j & 31;
    if (ln == 0) { r1[w] = v1; r2[w] = v2; }
    __syncthreads();
    float sum = 0.f, sq = 0.f;
    #pragma unroll
    for (int i = 0; i < 8; i++) { sum += r1[i]; sq += r2[i]; }
    float mean = sum * (1.0f/HH);
    float var  = sq * (1.0f/HH) - mean*mean;
    float inv  = rsqrtf(var + 1e-5f);
    g_x[(size_t)row*HH + j] = (s - mean)*inv*lng[j] + lnb[j];
}

// ---------------------------------------------------------------------------
// Heads
// ---------------------------------------------------------------------------
__device__ __forceinline__ float softplus_f(float x) {
    return fmaxf(x, 0.f) + log1pf(expf(-fabsf(x)));
}

__global__ void __launch_bounds__(256) head_kernel(
    const float* __restrict__ mu_w, const float* __restrict__ mu_b,
    const float* __restrict__ al_w, const float* __restrict__ al_b,
    float* __restrict__ out, int half)
{
    const int w = threadIdx.x >> 5, ln = threadIdx.x & 31;
    const int row = blockIdx.x*8 + w;
    const float* xr = g_x + (size_t)row*HH;
    float sm = 0.f, sa = 0.f;
    #pragma unroll
    for (int i = 0; i < 8; i++) {
        float v = xr[ln + i*32];
        sm = fmaf(v, mu_w[ln + i*32], sm);
        sa = fmaf(v, al_w[ln + i*32], sa);
    }
    #pragma unroll
    for (int o = 16; o > 0; o >>= 1) {
        sm += __shfl_xor_sync(0xffffffffu, sm, o);
        sa += __shfl_xor_sync(0xffffffffu, sa, o);
    }
    if (ln == 0) {
        out[row]        = softplus_f(sm + mu_b[0]);
        out[half + row] = softplus_f(sa + al_b[0]);
    }
}

// ---------------------------------------------------------------------------
extern "C" void kernel_launch(void* const* d_in, const int* in_sizes, int n_in,
                              void* d_out, int out_size)
{
    const float* x      = (const float*)d_in[0];
    const float* enc_w  = (const float*)d_in[1];
    const float* enc_b  = (const float*)d_in[2];
    const float* log_dt = (const float*)d_in[3];
    const float* logA   = (const float*)d_in[4];
    const float* A_im   = (const float*)d_in[5];
    const float* C_re   = (const float*)d_in[6];
    const float* C_im   = (const float*)d_in[7];
    const float* Dp     = (const float*)d_in[8];
    const float* out_w  = (const float*)d_in[9];
    const float* out_b  = (const float*)d_in[10];
    const float* ln_g   = (const float*)d_in[11];
    const float* ln_b   = (const float*)d_in[12];
    const float* mu_w   = (const float*)d_in[13];
    const float* mu_b   = (const float*)d_in[14];
    const float* al_w   = (const float*)d_in[15];
    const float* al_b   = (const float*)d_in[16];
    float* out = (float*)d_out;

    enc_kernel<<<GM, HH>>>(x, enc_w, enc_b);

    for (int l = 0; l < NLAYERS; l++) {
        scan_kernel<<<dim3(HH/16, BB), 128>>>(
            log_dt + l*HH,
            logA   + (size_t)l*HH*NN,
            A_im   + (size_t)l*HH*NN,
            C_re   + (size_t)l*HH*NN,
            C_im   + (size_t)l*HH*NN,
            Dp     + l*HH);
        gemm_glu_kernel<<<dim3(4, GM/128), 256>>>(
            out_w + (size_t)l*GN*GK,
            out_b + (size_t)l*GN);
        ln_kernel<<<GM, HH>>>(ln_g + l*HH, ln_b + l*HH);
    }

    head_kernel<<<GM/8, 256>>>(mu_w, mu_b, al_w, al_b, out, out_size/2);
}

// round 3
// speedup vs baseline: 1.4863x; 1.2758x over previous
#include <cuda_runtime.h>
#include <cuda_bf16.h>
#include <math.h>

// Problem constants
#define BB 16
#define LL 2048
#define DIN 8
#define HH 256
#define NN 64
#define NLAYERS 4
#define GM (BB*LL)      // 32768 rows
#define GK HH           // 256
#define GN (2*HH)       // 512

typedef unsigned long long ull;
typedef unsigned int u32;

// Scratch (device globals; no allocation allowed)
__device__ float g_x[(size_t)GM*HH];                    // activations (B,L,H)
__device__ float g_s[(size_t)GM*HH];                    // GLU+residual pre-LN
__device__ __nv_bfloat16 g_gh[(size_t)GM*HH];           // gelu out, bf16 hi
__device__ __nv_bfloat16 g_gl[(size_t)GM*HH];           // gelu out, bf16 lo
__device__ __nv_bfloat16 g_wh[(size_t)NLAYERS*GN*GK];   // W bf16 hi
__device__ __nv_bfloat16 g_wl[(size_t)NLAYERS*GN*GK];   // W bf16 lo

// ---------------------------------------------------------------------------
// packed f32x2 helpers
// ---------------------------------------------------------------------------
__device__ __forceinline__ ull f2_fma(ull a, ull b, ull c) {
    ull d; asm("fma.rn.f32x2 %0,%1,%2,%3;" : "=l"(d) : "l"(a), "l"(b), "l"(c)); return d;
}
__device__ __forceinline__ ull f2_mul(ull a, ull b) {
    ull d; asm("mul.rn.f32x2 %0,%1,%2;" : "=l"(d) : "l"(a), "l"(b)); return d;
}
__device__ __forceinline__ ull f2_pack(float lo, float hi) {
    ull d; asm("mov.b64 %0,{%1,%2};" : "=l"(d) : "f"(lo), "f"(hi)); return d;
}
__device__ __forceinline__ float f2_sum(ull v) {
    float lo, hi; asm("mov.b64 {%0,%1},%2;" : "=f"(lo), "=f"(hi) : "l"(v)); return lo + hi;
}

// ---------------------------------------------------------------------------
// Encoder
// ---------------------------------------------------------------------------
__global__ void enc_kernel(const float* __restrict__ x,
                           const float* __restrict__ w,
                           const float* __restrict__ b)
{
    int row = blockIdx.x;
    int h = threadIdx.x;
    __shared__ float xr[DIN];
    if (h < DIN) xr[h] = x[row*DIN + h];
    __syncthreads();
    float s = b[h];
    #pragma unroll
    for (int k = 0; k < DIN; k++)
        s = fmaf(xr[k], w[h*DIN + k], s);
    g_x[(size_t)row*HH + h] = s;
}

// ---------------------------------------------------------------------------
// One-shot W -> bf16 hi/lo split (all layers)
// ---------------------------------------------------------------------------
__global__ void wconv_kernel(const float* __restrict__ W)
{
    size_t i = (size_t)blockIdx.x*256 + threadIdx.x;   // < NLAYERS*GN*GK
    float w = W[i];
    __nv_bfloat16 h = __float2bfloat16_rn(w);
    g_wh[i] = h;
    g_wl[i] = __float2bfloat16_rn(w - __bfloat162float(h));
}

// ---------------------------------------------------------------------------
// S4D scan (f32x2 recurrence), output written as bf16 hi/lo split
// ---------------------------------------------------------------------------
__global__ void __launch_bounds__(128) scan_kernel(
    const float* __restrict__ log_dt,
    const float* __restrict__ logA_re,
    const float* __restrict__ A_im,
    const float* __restrict__ C_re,
    const float* __restrict__ C_im,
    const float* __restrict__ Dp)
{
    const int b  = blockIdx.y;
    const int h0 = blockIdx.x * 16;
    const int tid = threadIdx.x;
    const int w = tid >> 5, lane = tid & 31;
    const int cw = lane >> 3;
    const int sl = lane & 7;
    const int cb = w*4 + cw;
    const int h = h0 + cb;

    float lr[8], li[8], cr[8], ci[8];
    const float dt = expf(log_dt[h]);
    #pragma unroll
    for (int j = 0; j < 8; j++) {
        int n = sl*8 + j;
        int idx = h*NN + n;
        float are = -expf(logA_re[idx]);
        float aim = A_im[idx];
        float dre = dt*are, dim = dt*aim;
        float er = expf(dre);
        float Lr = er*cosf(dim), Li = er*sinf(dim);
        lr[j] = Lr; li[j] = Li;
        float Cre = C_re[idx], Cim = C_im[idx];
        float nr = Lr - 1.0f, ni = Li;
        float tr = Cre*nr - Cim*ni;
        float ti = Cre*ni + Cim*nr;
        float inv = 2.0f / (are*are + aim*aim);
        cr[j] =  inv*(tr*are + ti*aim);
        ci[j] = -inv*(ti*are - tr*aim);
    }

    ull lr2[4], li2[4], nli2[4], cr2[4], ci2[4], zr2[4], zi2[4];
    #pragma unroll
    for (int q = 0; q < 4; q++) {
        lr2[q]  = f2_pack(lr[2*q],  lr[2*q+1]);
        li2[q]  = f2_pack(li[2*q],  li[2*q+1]);
        nli2[q] = f2_pack(-li[2*q], -li[2*q+1]);
        cr2[q]  = f2_pack(cr[2*q],  cr[2*q+1]);
        ci2[q]  = f2_pack(ci[2*q],  ci[2*q+1]);
        zr2[q]  = 0ull;
        zi2[q]  = 0ull;
    }

    __shared__ float u_s[32][17];
    __shared__ float y_s[32][17];
    __shared__ float D_s[16];
    if (tid < 16) D_s[tid] = Dp[h0 + tid];

    const float* xb = g_x + (size_t)b*LL*HH + h0;
    __nv_bfloat16* gh = g_gh + (size_t)b*LL*HH + h0;
    __nv_bfloat16* gl = g_gl + (size_t)b*LL*HH + h0;

    for (int tc = 0; tc < LL/32; tc++) {
        __syncthreads();
        #pragma unroll
        for (int i = 0; i < 4; i++) {
            int e = tid + i*128;
            int tt = e >> 4, hh = e & 15;
            u_s[tt][hh] = xb[(size_t)(tc*32 + tt)*HH + hh];
        }
        __syncthreads();

        #pragma unroll 4
        for (int j = 0; j < 32; j++) {
            float u = u_s[j][cb];
            ull u2 = f2_pack(u, u);
            ull p2;
            {
                ull t = f2_fma(lr2[0], zr2[0], u2);
                t = f2_fma(nli2[0], zi2[0], t);
                ull s = f2_mul(li2[0], zr2[0]);
                s = f2_fma(lr2[0], zi2[0], s);
                zr2[0] = t; zi2[0] = s;
                p2 = f2_mul(cr2[0], t);
                p2 = f2_fma(ci2[0], s, p2);
            }
            #pragma unroll
            for (int q = 1; q < 4; q++) {
                ull t = f2_fma(lr2[q], zr2[q], u2);
                t = f2_fma(nli2[q], zi2[q], t);
                ull s = f2_mul(li2[q], zr2[q]);
                s = f2_fma(lr2[q], zi2[q], s);
                zr2[q] = t; zi2[q] = s;
                p2 = f2_fma(cr2[q], t, p2);
                p2 = f2_fma(ci2[q], s, p2);
            }
            float p = f2_sum(p2);
            p += __shfl_xor_sync(0xffffffffu, p, 4);
            p += __shfl_xor_sync(0xffffffffu, p, 2);
            p += __shfl_xor_sync(0xffffffffu, p, 1);
            if (sl == 0) y_s[j][cb] = p;
        }
        __syncthreads();

        #pragma unroll
        for (int i = 0; i < 4; i++) {
            int e = tid + i*128;
            int tt = e >> 4, hh = e & 15;
            float uu = u_s[tt][hh];
            float yv = fmaf(D_s[hh], uu, y_s[tt][hh]);
            float gv = 0.5f*yv*(1.0f + erff(yv*0.70710678118654752f));
            __nv_bfloat16 hv = __float2bfloat16_rn(gv);
            size_t o = (size_t)(tc*32 + tt)*HH + hh;
            gh[o] = hv;
            gl[o] = __float2bfloat16_rn(gv - __bfloat162float(hv));
        }
    }
}

// ---------------------------------------------------------------------------
// bf16x3 tensor-core GEMM + fused GLU/bias/residual.
//   Virtual K = 768: regions (Ah,Bh), (Al,Bh), (Ah,Bl); k-chunk 32;
//   3-stage cp.async pipeline; xor-swizzled smem; ldmatrix.x4; mma.m16n8k16.
//   Block: 128 rows x 128 gemm-cols (= 64 GLU pairs). 8 warps = 4m x 2n.
// ---------------------------------------------------------------------------
__device__ __forceinline__ void cp16(u32 dst, const void* src) {
    asm volatile("cp.async.cg.shared.global [%0], [%1], 16;" :: "r"(dst), "l"(src));
}
__device__ __forceinline__ void ldsm4(u32& r0, u32& r1, u32& r2, u32& r3, u32 addr) {
    asm volatile("ldmatrix.sync.aligned.m8n8.x4.shared.b16 {%0,%1,%2,%3},[%4];"
                 : "=r"(r0), "=r"(r1), "=r"(r2), "=r"(r3) : "r"(addr));
}
__device__ __forceinline__ void mma_bf16(float* d, const u32* a, const u32* b) {
    asm volatile(
        "mma.sync.aligned.m16n8k16.row.col.f32.bf16.bf16.f32 "
        "{%0,%1,%2,%3},{%4,%5,%6,%7},{%8,%9},{%0,%1,%2,%3};"
        : "+f"(d[0]), "+f"(d[1]), "+f"(d[2]), "+f"(d[3])
        : "r"(a[0]), "r"(a[1]), "r"(a[2]), "r"(a[3]), "r"(b[0]), "r"(b[1]));
}

#define NCHUNK 24   // 3 regions x (256/32)

__global__ void __launch_bounds__(256) gemm_glu_kernel(int l, const float* __restrict__ bias)
{
    __shared__ __align__(128) char smem_buf[3*16384];   // 3 stages x (A 8KB + B 8KB)

    const int m0  = blockIdx.y * 128;
    const int nb  = blockIdx.x;
    const int tid = threadIdx.x;
    const int lane = tid & 31, w = tid >> 5;
    const int wm = w & 3;           // m quarter (32 rows)
    const int wn = w >> 2;          // n half (64 gemm cols)

    const __nv_bfloat16* Wh = g_wh + (size_t)l*GN*GK;
    const __nv_bfloat16* Wl = g_wl + (size_t)l*GN*GK;

    const u32 smem_base = (u32)__cvta_generic_to_shared(smem_buf);

    float acc[2][8][4];
    #pragma unroll
    for (int mi = 0; mi < 2; mi++)
        #pragma unroll
        for (int ni = 0; ni < 8; ni++)
            #pragma unroll
            for (int r = 0; r < 4; r++) acc[mi][ni][r] = 0.f;

    // ---- chunk loader ----
    auto load_chunk = [&](int kc, int stage) {
        int region = kc >> 3;
        int k0 = (kc & 7) * 32;
        const __nv_bfloat16* Asrc = (region == 1) ? g_gl : g_gh;
        const __nv_bfloat16* Bsrc = (region == 2) ? Wl : Wh;
        u32 abase = smem_base + stage*16384;
        u32 bbase = abase + 8192;
        #pragma unroll
        for (int i = 0; i < 2; i++) {
            int gid = i*256 + tid;
            int row = gid >> 2, g = gid & 3;
            int pg = g ^ ((row >> 1) & 3);
            cp16(abase + row*64 + pg*16, Asrc + (size_t)(m0 + row)*GK + k0 + g*8);
            int wr = nb*64 + (row >> 1) + (row & 1)*256;
            cp16(bbase + row*64 + pg*16, Bsrc + (size_t)wr*GK + k0 + g*8);
        }
    };

    // prologue: stages 0,1
    load_chunk(0, 0);
    asm volatile("cp.async.commit_group;");
    load_chunk(1, 1);
    asm volatile("cp.async.commit_group;");

    for (int kc = 0; kc < NCHUNK; kc++) {
        if (kc + 2 < NCHUNK) load_chunk(kc + 2, (kc + 2) % 3);
        asm volatile("cp.async.commit_group;");
        asm volatile("cp.async.wait_group 2;");
        __syncthreads();

        const int stage = kc % 3;
        const u32 abase = smem_base + stage*16384;
        const u32 bbase = abase + 8192;

        #pragma unroll
        for (int ks = 0; ks < 2; ks++) {
            const int grp = lane >> 3, rh = lane & 7;
            u32 a[2][4];
            #pragma unroll
            for (int mi = 0; mi < 2; mi++) {
                int row = wm*32 + mi*16 + rh + (grp & 1)*8;
                int kg  = 2*ks + (grp >> 1);
                u32 addr = abase + row*64 + ((kg ^ ((row >> 1) & 3))*16);
                ldsm4(a[mi][0], a[mi][1], a[mi][2], a[mi][3], addr);
            }
            u32 bfr[8][2];
            #pragma unroll
            for (int nf = 0; nf < 4; nf++) {
                int row = wn*64 + nf*16 + rh + (grp >> 1)*8;
                int kg  = 2*ks + (grp & 1);
                u32 addr = bbase + row*64 + ((kg ^ ((row >> 1) & 3))*16);
                u32 r0, r1, r2, r3;
                ldsm4(r0, r1, r2, r3, addr);
                bfr[nf*2][0] = r0; bfr[nf*2][1] = r1;
                bfr[nf*2+1][0] = r2; bfr[nf*2+1][1] = r3;
            }
            #pragma unroll
            for (int mi = 0; mi < 2; mi++)
                #pragma unroll
                for (int ni = 0; ni < 8; ni++)
                    mma_bf16(acc[mi][ni], a[mi], bfr[ni]);
        }
        __syncthreads();
    }

    // Epilogue: GLU + bias + residual -> g_s
    const int lc = lane & 3, lq = lane >> 2;
    #pragma unroll
    for (int ni = 0; ni < 8; ni++) {
        const int oc = nb*64 + wn*32 + ni*4 + lc;    // 0..255
        const float bL = bias[oc];
        const float bR = bias[oc + 256];
        #pragma unroll
        for (int mi = 0; mi < 2; mi++) {
            int mg = m0 + wm*32 + mi*16 + lq;
            {
                float zl = acc[mi][ni][0] + bL;
                float zr_ = acc[mi][ni][1] + bR;
                float sv = zl * (1.0f/(1.0f + expf(-zr_))) + g_x[(size_t)mg*HH + oc];
                g_s[(size_t)mg*HH + oc] = sv;
            }
            {
                int mg2 = mg + 8;
                float zl = acc[mi][ni][2] + bL;
                float zr_ = acc[mi][ni][3] + bR;
                float sv = zl * (1.0f/(1.0f + expf(-zr_))) + g_x[(size_t)mg2*HH + oc];
                g_s[(size_t)mg2*HH + oc] = sv;
            }
        }
    }
}

// ---------------------------------------------------------------------------
// LayerNorm, warp-per-row (float4). Optionally fused softplus heads.
// ---------------------------------------------------------------------------
__device__ __forceinline__ float softplus_f(float x) {
    return fmaxf(x, 0.f) + log1pf(expf(-fabsf(x)));
}

__global__ void __launch_bounds__(256) ln_kernel(
    const float* __restrict__ lng, const float* __restrict__ lnb,
    const float* __restrict__ mu_w, const float* __restrict__ mu_b,
    const float* __restrict__ al_w, const float* __restrict__ al_b,
    float* __restrict__ out, int half, int do_head)
{
    const int w = threadIdx.x >> 5, lane = threadIdx.x & 31;
    const int row = blockIdx.x*8 + w;
    const float4* sp = (const float4*)(g_s + (size_t)row*HH);
    float4 v0 = sp[lane];
    float4 v1 = sp[lane + 32];

    float s1 = v0.x+v0.y+v0.z+v0.w + v1.x+v1.y+v1.z+v1.w;
    float s2 = v0.x*v0.x+v0.y*v0.y+v0.z*v0.z+v0.w*v0.w
             + v1.x*v1.x+v1.y*v1.y+v1.z*v1.z+v1.w*v1.w;
    #pragma unroll
    for (int o = 16; o > 0; o >>= 1) {
        s1 += __shfl_xor_sync(0xffffffffu, s1, o);
        s2 += __shfl_xor_sync(0xffffffffu, s2, o);
    }
    float mean = s1 * (1.0f/HH);
    float var  = s2 * (1.0f/HH) - mean*mean;
    float inv  = rsqrtf(var + 1e-5f);

    const float4* gp = (const float4*)lng;
    const float4* bp = (const float4*)lnb;
    float4 g0 = gp[lane], g1 = gp[lane+32];
    float4 b0 = bp[lane], b1 = bp[lane+32];
    float4 y0, y1;
    y0.x = (v0.x-mean)*inv*g0.x + b0.x;  y0.y = (v0.y-mean)*inv*g0.y + b0.y;
    y0.z = (v0.z-mean)*inv*g0.z + b0.z;  y0.w = (v0.w-mean)*inv*g0.w + b0.w;
    y1.x = (v1.x-mean)*inv*g1.x + b1.x;  y1.y = (v1.y-mean)*inv*g1.y + b1.y;
    y1.z = (v1.z-mean)*inv*g1.z + b1.z;  y1.w = (v1.w-mean)*inv*g1.w + b1.w;

    float4* xp = (float4*)(g_x + (size_t)row*HH);
    xp[lane] = y0;
    xp[lane + 32] = y1;

    if (do_head) {
        const float4* mp = (const float4*)mu_w;
        const float4* ap = (const float4*)al_w;
        float4 m0 = mp[lane], m1 = mp[lane+32];
        float4 a0 = ap[lane], a1 = ap[lane+32];
        float sm = y0.x*m0.x + y0.y*m0.y + y0.z*m0.z + y0.w*m0.w
                 + y1.x*m1.x + y1.y*m1.y + y1.z*m1.z + y1.w*m1.w;
        float sa = y0.x*a0.x + y0.y*a0.y + y0.z*a0.z + y0.w*a0.w
                 + y1.x*a1.x + y1.y*a1.y + y1.z*a1.z + y1.w*a1.w;
        #pragma unroll
        for (int o = 16; o > 0; o >>= 1) {
            sm += __shfl_xor_sync(0xffffffffu, sm, o);
            sa += __shfl_xor_sync(0xffffffffu, sa, o);
        }
        if (lane == 0) {
            out[row]        = softplus_f(sm + mu_b[0]);
            out[half + row] = softplus_f(sa + al_b[0]);
        }
    }
}

// ---------------------------------------------------------------------------
extern "C" void kernel_launch(void* const* d_in, const int* in_sizes, int n_in,
                              void* d_out, int out_size)
{
    const float* x      = (const float*)d_in[0];
    const float* enc_w  = (const float*)d_in[1];
    const float* enc_b  = (const float*)d_in[2];
    const float* log_dt = (const float*)d_in[3];
    const float* logA   = (const float*)d_in[4];
    const float* A_im   = (const float*)d_in[5];
    const float* C_re   = (const float*)d_in[6];
    const float* C_im   = (const float*)d_in[7];
    const float* Dp     = (const float*)d_in[8];
    const float* out_w  = (const float*)d_in[9];
    const float* out_b  = (const float*)d_in[10];
    const float* ln_g   = (const float*)d_in[11];
    const float* ln_b   = (const float*)d_in[12];
    const float* mu_w   = (const float*)d_in[13];
    const float* mu_b   = (const float*)d_in[14];
    const float* al_w   = (const float*)d_in[15];
    const float* al_b   = (const float*)d_in[16];
    float* out = (float*)d_out;

    enc_kernel<<<GM, HH>>>(x, enc_w, enc_b);
    wconv_kernel<<<(NLAYERS*GN*GK)/256, 256>>>(out_w);

    for (int l = 0; l < NLAYERS; l++) {
        scan_kernel<<<dim3(HH/16, BB), 128>>>(
            log_dt + l*HH,
            logA   + (size_t)l*HH*NN,
            A_im   + (size_t)l*HH*NN,
            C_re   + (size_t)l*HH*NN,
            C_im   + (size_t)l*HH*NN,
            Dp     + l*HH);
        gemm_glu_kernel<<<dim3(4, GM/128), 256>>>(l, out_b + (size_t)l*GN);
        ln_kernel<<<GM/8, 256>>>(ln_g + l*HH, ln_b + l*HH,
                                 mu_w, mu_b, al_w, al_b,
                                 out, out_size/2, (l == NLAYERS-1) ? 1 : 0);
    }
}

// round 4
// speedup vs baseline: 1.5410x; 1.0368x over previous
#include <cuda_runtime.h>
#include <cuda_bf16.h>
#include <math.h>

// Problem constants
#define BB 16
#define LL 2048
#define DIN 8
#define HH 256
#define NN 64
#define NLAYERS 4
#define GM (BB*LL)      // 32768 rows
#define GK HH           // 256
#define GN (2*HH)       // 512
#define NC 16           // time chunks
#define TT (LL/NC)      // 128 steps per chunk

typedef unsigned long long ull;
typedef unsigned int u32;

// Scratch (device globals; no allocation allowed)
__device__ float g_x[(size_t)GM*HH];                    // activations (B,L,H)
__device__ float g_s[(size_t)GM*HH];                    // GLU+residual pre-LN
__device__ __nv_bfloat16 g_gh[(size_t)GM*HH];           // gelu out, bf16 hi
__device__ __nv_bfloat16 g_gl[(size_t)GM*HH];           // gelu out, bf16 lo
__device__ __nv_bfloat16 g_wh[(size_t)NLAYERS*GN*GK];   // W bf16 hi
__device__ __nv_bfloat16 g_wl[(size_t)NLAYERS*GN*GK];   // W bf16 lo
__device__ float g_zc[(size_t)BB*NC*HH*NN*2];           // chunk states (re,im)

// ---------------------------------------------------------------------------
// packed f32x2 helpers
// ---------------------------------------------------------------------------
__device__ __forceinline__ ull f2_fma(ull a, ull b, ull c) {
    ull d; asm("fma.rn.f32x2 %0,%1,%2,%3;" : "=l"(d) : "l"(a), "l"(b), "l"(c)); return d;
}
__device__ __forceinline__ ull f2_mul(ull a, ull b) {
    ull d; asm("mul.rn.f32x2 %0,%1,%2;" : "=l"(d) : "l"(a), "l"(b)); return d;
}
__device__ __forceinline__ ull f2_pack(float lo, float hi) {
    ull d; asm("mov.b64 %0,{%1,%2};" : "=l"(d) : "f"(lo), "f"(hi)); return d;
}
__device__ __forceinline__ void f2_unpack(ull v, float& lo, float& hi) {
    asm("mov.b64 {%0,%1},%2;" : "=f"(lo), "=f"(hi) : "l"(v));
}
__device__ __forceinline__ float f2_sum(ull v) {
    float lo, hi; f2_unpack(v, lo, hi); return lo + hi;
}

// ---------------------------------------------------------------------------
// Encoder
// ---------------------------------------------------------------------------
__global__ void enc_kernel(const float* __restrict__ x,
                           const float* __restrict__ w,
                           const float* __restrict__ b)
{
    int row = blockIdx.x;
    int h = threadIdx.x;
    __shared__ float xr[DIN];
    if (h < DIN) xr[h] = x[row*DIN + h];
    __syncthreads();
    float s = b[h];
    #pragma unroll
    for (int k = 0; k < DIN; k++)
        s = fmaf(xr[k], w[h*DIN + k], s);
    g_x[(size_t)row*HH + h] = s;
}

// ---------------------------------------------------------------------------
// One-shot W -> bf16 hi/lo split
// ---------------------------------------------------------------------------
__global__ void wconv_kernel(const float* __restrict__ W)
{
    size_t i = (size_t)blockIdx.x*256 + threadIdx.x;
    float w = W[i];
    __nv_bfloat16 h = __float2bfloat16_rn(w);
    g_wh[i] = h;
    g_wl[i] = __float2bfloat16_rn(w - __bfloat162float(h));
}

// ---------------------------------------------------------------------------
// Shared per-channel S4D parameter setup
// ---------------------------------------------------------------------------
__device__ __forceinline__ void s4_lambda(
    const float* log_dt, const float* logA_re, const float* A_im,
    int h, int n, float& Lr, float& Li, float& are, float& aim)
{
    float dt = expf(log_dt[h]);
    are = -expf(logA_re[h*NN + n]);
    aim = A_im[h*NN + n];
    float er = expf(dt*are);
    float dim = dt*aim;
    Lr = er*cosf(dim);
    Li = er*sinf(dim);
}

// ---------------------------------------------------------------------------
// scan1: per-(channel,chunk) recurrence from z=0; store end state. No output.
//   grid (H/16, B, NC), block 128.
// ---------------------------------------------------------------------------
__global__ void __launch_bounds__(128) scan1_kernel(
    const float* __restrict__ log_dt,
    const float* __restrict__ logA_re,
    const float* __restrict__ A_im)
{
    const int b  = blockIdx.y;
    const int c  = blockIdx.z;
    const int h0 = blockIdx.x * 16;
    const int tid = threadIdx.x;
    const int w = tid >> 5, lane = tid & 31;
    const int cw = lane >> 3;
    const int sl = lane & 7;
    const int cb = w*4 + cw;
    const int h = h0 + cb;

    float lr[8], li[8];
    #pragma unroll
    for (int j = 0; j < 8; j++) {
        float are, aim;
        s4_lambda(log_dt, logA_re, A_im, h, sl*8 + j, lr[j], li[j], are, aim);
    }
    ull lr2[4], li2[4], nli2[4], zr2[4], zi2[4];
    #pragma unroll
    for (int q = 0; q < 4; q++) {
        lr2[q]  = f2_pack(lr[2*q],  lr[2*q+1]);
        li2[q]  = f2_pack(li[2*q],  li[2*q+1]);
        nli2[q] = f2_pack(-li[2*q], -li[2*q+1]);
        zr2[q] = 0ull; zi2[q] = 0ull;
    }

    __shared__ float u_s[32][17];
    const float* xb = g_x + (size_t)b*LL*HH + (size_t)c*TT*HH + h0;

    for (int tc = 0; tc < TT/32; tc++) {
        __syncthreads();
        #pragma unroll
        for (int i = 0; i < 4; i++) {
            int e = tid + i*128;
            int tt = e >> 4, hh = e & 15;
            u_s[tt][hh] = xb[(size_t)(tc*32 + tt)*HH + hh];
        }
        __syncthreads();

        #pragma unroll 4
        for (int j = 0; j < 32; j++) {
            ull u2 = f2_pack(u_s[j][cb], u_s[j][cb]);
            #pragma unroll
            for (int q = 0; q < 4; q++) {
                ull t = f2_fma(lr2[q], zr2[q], u2);
                t = f2_fma(nli2[q], zi2[q], t);
                ull s = f2_mul(li2[q], zr2[q]);
                s = f2_fma(lr2[q], zi2[q], s);
                zr2[q] = t; zi2[q] = s;
            }
        }
    }

    // store end state
    float* zb = g_zc + ((((size_t)b*NC + c)*HH + h)*NN + sl*8)*2;
    #pragma unroll
    for (int q = 0; q < 4; q++) {
        float r0, r1, i0, i1;
        f2_unpack(zr2[q], r0, r1);
        f2_unpack(zi2[q], i0, i1);
        float4 v; v.x = r0; v.y = i0; v.z = r1; v.w = i1;
        *(float4*)(zb + q*4) = v;
    }
}

// ---------------------------------------------------------------------------
// scan_fix: compose chunk summaries -> true initial state per chunk.
//   One thread per (b,h,n). z0[0]=0; z0[c]=Λ z0[c-1] + zend[c-1], Λ=λ^T.
// ---------------------------------------------------------------------------
__global__ void __launch_bounds__(256) scanfix_kernel(
    const float* __restrict__ log_dt,
    const float* __restrict__ logA_re,
    const float* __restrict__ A_im)
{
    int gid = blockIdx.x*256 + threadIdx.x;       // < BB*HH*NN
    int n = gid & (NN-1);
    int h = (gid >> 6) & (HH-1);
    int b = gid >> 14;

    float Lr, Li, are, aim;
    s4_lambda(log_dt, logA_re, A_im, h, n, Lr, Li, are, aim);
    // Λ = λ^TT via squaring (TT=128 -> 7 squarings)
    #pragma unroll
    for (int s = 0; s < 7; s++) {
        float nr = Lr*Lr - Li*Li;
        float ni = 2.0f*Lr*Li;
        Lr = nr; Li = ni;
    }

    float2* zb = (float2*)g_zc;
    float cr = 0.f, ci = 0.f;
    #pragma unroll
    for (int c = 0; c < NC; c++) {
        size_t idx = (((size_t)b*NC + c)*HH + h)*NN + n;
        float2 ze = zb[idx];
        zb[idx] = make_float2(cr, ci);
        float nr = Lr*cr - Li*ci + ze.x;
        float ni = Lr*ci + Li*cr + ze.y;
        cr = nr; ci = ni;
    }
}

// ---------------------------------------------------------------------------
// scan2: recurrence per chunk from corrected z0; emit gelu as bf16 hi/lo.
//   grid (H/16, B, NC), block 128.
// ---------------------------------------------------------------------------
__global__ void __launch_bounds__(128) scan2_kernel(
    const float* __restrict__ log_dt,
    const float* __restrict__ logA_re,
    const float* __restrict__ A_im,
    const float* __restrict__ C_re,
    const float* __restrict__ C_im,
    const float* __restrict__ Dp)
{
    const int b  = blockIdx.y;
    const int c  = blockIdx.z;
    const int h0 = blockIdx.x * 16;
    const int tid = threadIdx.x;
    const int w = tid >> 5, lane = tid & 31;
    const int cw = lane >> 3;
    const int sl = lane & 7;
    const int cb = w*4 + cw;
    const int h = h0 + cb;

    float lr[8], li[8], cr[8], ci[8];
    #pragma unroll
    for (int j = 0; j < 8; j++) {
        int n = sl*8 + j;
        float are, aim;
        s4_lambda(log_dt, logA_re, A_im, h, n, lr[j], li[j], are, aim);
        float Cre = C_re[h*NN + n], Cim = C_im[h*NN + n];
        float nr = lr[j] - 1.0f, ni = li[j];
        float tr = Cre*nr - Cim*ni;
        float ti = Cre*ni + Cim*nr;
        float inv = 2.0f / (are*are + aim*aim);
        cr[j] =  inv*(tr*are + ti*aim);
        ci[j] = -inv*(ti*are - tr*aim);
    }

    ull lr2[4], li2[4], nli2[4], cr2[4], ci2[4], zr2[4], zi2[4];
    const float* zb = g_zc + ((((size_t)b*NC + c)*HH + h)*NN + sl*8)*2;
    #pragma unroll
    for (int q = 0; q < 4; q++) {
        lr2[q]  = f2_pack(lr[2*q],  lr[2*q+1]);
        li2[q]  = f2_pack(li[2*q],  li[2*q+1]);
        nli2[q] = f2_pack(-li[2*q], -li[2*q+1]);
        cr2[q]  = f2_pack(cr[2*q],  cr[2*q+1]);
        ci2[q]  = f2_pack(ci[2*q],  ci[2*q+1]);
        float4 v = *(const float4*)(zb + q*4);
        zr2[q] = f2_pack(v.x, v.z);
        zi2[q] = f2_pack(v.y, v.w);
    }

    __shared__ float u_s[32][17];
    __shared__ float y_s[32][17];
    __shared__ float D_s[16];
    if (tid < 16) D_s[tid] = Dp[h0 + tid];

    const float* xb = g_x + (size_t)b*LL*HH + (size_t)c*TT*HH + h0;
    __nv_bfloat16* gh = g_gh + (size_t)b*LL*HH + (size_t)c*TT*HH + h0;
    __nv_bfloat16* gl = g_gl + (size_t)b*LL*HH + (size_t)c*TT*HH + h0;

    for (int tc = 0; tc < TT/32; tc++) {
        __syncthreads();
        #pragma unroll
        for (int i = 0; i < 4; i++) {
            int e = tid + i*128;
            int tt = e >> 4, hh = e & 15;
            u_s[tt][hh] = xb[(size_t)(tc*32 + tt)*HH + hh];
        }
        __syncthreads();

        #pragma unroll 4
        for (int j = 0; j < 32; j++) {
            float u = u_s[j][cb];
            ull u2 = f2_pack(u, u);
            ull p2;
            {
                ull t = f2_fma(lr2[0], zr2[0], u2);
                t = f2_fma(nli2[0], zi2[0], t);
                ull s = f2_mul(li2[0], zr2[0]);
                s = f2_fma(lr2[0], zi2[0], s);
                zr2[0] = t; zi2[0] = s;
                p2 = f2_mul(cr2[0], t);
                p2 = f2_fma(ci2[0], s, p2);
            }
            #pragma unroll
            for (int q = 1; q < 4; q++) {
                ull t = f2_fma(lr2[q], zr2[q], u2);
                t = f2_fma(nli2[q], zi2[q], t);
                ull s = f2_mul(li2[q], zr2[q]);
                s = f2_fma(lr2[q], zi2[q], s);
                zr2[q] = t; zi2[q] = s;
                p2 = f2_fma(cr2[q], t, p2);
                p2 = f2_fma(ci2[q], s, p2);
            }
            float p = f2_sum(p2);
            p += __shfl_xor_sync(0xffffffffu, p, 4);
            p += __shfl_xor_sync(0xffffffffu, p, 2);
            p += __shfl_xor_sync(0xffffffffu, p, 1);
            if (sl == 0) y_s[j][cb] = p;
        }
        __syncthreads();

        #pragma unroll
        for (int i = 0; i < 4; i++) {
            int e = tid + i*128;
            int tt = e >> 4, hh = e & 15;
            float uu = u_s[tt][hh];
            float yv = fmaf(D_s[hh], uu, y_s[tt][hh]);
            float gv = 0.5f*yv*(1.0f + erff(yv*0.70710678118654752f));
            __nv_bfloat16 hv = __float2bfloat16_rn(gv);
            size_t o = (size_t)(tc*32 + tt)*HH + hh;
            gh[o] = hv;
            gl[o] = __float2bfloat16_rn(gv - __bfloat162float(hv));
        }
    }
}

// ---------------------------------------------------------------------------
// bf16x3 tensor-core GEMM + fused GLU/bias/residual.
//   Block 256 thr, tile 128 rows x 64 gemm cols (32 GLU pairs).
//   8 warps = 4m x 2n, warp tile 32x32. 3-stage cp.async, swizzled ldmatrix.
// ---------------------------------------------------------------------------
__device__ __forceinline__ void cp16(u32 dst, const void* src) {
    asm volatile("cp.async.cg.shared.global [%0], [%1], 16;" :: "r"(dst), "l"(src));
}
__device__ __forceinline__ void ldsm4(u32& r0, u32& r1, u32& r2, u32& r3, u32 addr) {
    asm volatile("ldmatrix.sync.aligned.m8n8.x4.shared.b16 {%0,%1,%2,%3},[%4];"
                 : "=r"(r0), "=r"(r1), "=r"(r2), "=r"(r3) : "r"(addr));
}
__device__ __forceinline__ void mma_bf16(float* d, const u32* a, const u32* b) {
    asm volatile(
        "mma.sync.aligned.m16n8k16.row.col.f32.bf16.bf16.f32 "
        "{%0,%1,%2,%3},{%4,%5,%6,%7},{%8,%9},{%0,%1,%2,%3};"
        : "+f"(d[0]), "+f"(d[1]), "+f"(d[2]), "+f"(d[3])
        : "r"(a[0]), "r"(a[1]), "r"(a[2]), "r"(a[3]), "r"(b[0]), "r"(b[1]));
}

#define NCHUNK 24       // 3 regions x (256/32)
#define STG 12288       // per-stage smem: A 8KB + B 4KB

__global__ void __launch_bounds__(256) gemm_glu_kernel(int l, const float* __restrict__ bias)
{
    __shared__ __align__(128) char smem_buf[3*STG];

    const int m0  = blockIdx.y * 128;
    const int nb  = blockIdx.x;       // 0..7, 32 GLU pairs each
    const int tid = threadIdx.x;
    const int lane = tid & 31, w = tid >> 5;
    const int wm = w & 3;             // m quarter (32 rows)
    const int wn = w >> 2;            // n half (32 gemm cols)

    const __nv_bfloat16* Wh = g_wh + (size_t)l*GN*GK;
    const __nv_bfloat16* Wl = g_wl + (size_t)l*GN*GK;

    const u32 smem_base = (u32)__cvta_generic_to_shared(smem_buf);

    float acc[2][4][4];
    #pragma unroll
    for (int mi = 0; mi < 2; mi++)
        #pragma unroll
        for (int ni = 0; ni < 4; ni++)
            #pragma unroll
            for (int r = 0; r < 4; r++) acc[mi][ni][r] = 0.f;

    auto load_chunk = [&](int kc, int stage) {
        int region = kc >> 3;
        int k0 = (kc & 7) * 32;
        const __nv_bfloat16* Asrc = (region == 1) ? g_gl : g_gh;
        const __nv_bfloat16* Bsrc = (region == 2) ? Wl : Wh;
        u32 abase = smem_base + stage*STG;
        u32 bbase = abase + 8192;
        #pragma unroll
        for (int i = 0; i < 2; i++) {
            int gid = i*256 + tid;
            int row = gid >> 2, g = gid & 3;
            int pg = g ^ ((row >> 1) & 3);
            cp16(abase + row*64 + pg*16, Asrc + (size_t)(m0 + row)*GK + k0 + g*8);
        }
        {
            int row = tid >> 2, g = tid & 3;    // row 0..63
            int pg = g ^ ((row >> 1) & 3);
            int wr = nb*32 + (row >> 1) + (row & 1)*256;
            cp16(bbase + row*64 + pg*16, Bsrc + (size_t)wr*GK + k0 + g*8);
        }
    };

    load_chunk(0, 0);
    asm volatile("cp.async.commit_group;");
    load_chunk(1, 1);
    asm volatile("cp.async.commit_group;");

    for (int kc = 0; kc < NCHUNK; kc++) {
        if (kc + 2 < NCHUNK) load_chunk(kc + 2, (kc + 2) % 3);
        asm volatile("cp.async.commit_group;");
        asm volatile("cp.async.wait_group 2;");
        __syncthreads();

        const int stage = kc % 3;
        const u32 abase = smem_base + stage*STG;
        const u32 bbase = abase + 8192;

        #pragma unroll
        for (int ks = 0; ks < 2; ks++) {
            const int grp = lane >> 3, rh = lane & 7;
            u32 a[2][4];
            #pragma unroll
            for (int mi = 0; mi < 2; mi++) {
                int row = wm*32 + mi*16 + rh + (grp & 1)*8;
                int kg  = 2*ks + (grp >> 1);
                u32 addr = abase + row*64 + ((kg ^ ((row >> 1) & 3))*16);
                ldsm4(a[mi][0], a[mi][1], a[mi][2], a[mi][3], addr);
            }
            u32 bfr[4][2];
            #pragma unroll
            for (int nf = 0; nf < 2; nf++) {
                int row = wn*32 + nf*16 + rh + (grp >> 1)*8;
                int kg  = 2*ks + (grp & 1);
                u32 addr = bbase + row*64 + ((kg ^ ((row >> 1) & 3))*16);
                u32 r0, r1, r2, r3;
                ldsm4(r0, r1, r2, r3, addr);
                bfr[nf*2][0] = r0; bfr[nf*2][1] = r1;
                bfr[nf*2+1][0] = r2; bfr[nf*2+1][1] = r3;
            }
            #pragma unroll
            for (int mi = 0; mi < 2; mi++)
                #pragma unroll
                for (int ni = 0; ni < 4; ni++)
                    mma_bf16(acc[mi][ni], a[mi], bfr[ni]);
        }
        __syncthreads();
    }

    // Epilogue: GLU + bias + residual -> g_s
    const int lc = lane & 3, lq = lane >> 2;
    #pragma unroll
    for (int ni = 0; ni < 4; ni++) {
        const int oc = nb*32 + wn*16 + ni*4 + lc;    // 0..255
        const float bL = bias[oc];
        const float bR = bias[oc + 256];
        #pragma unroll
        for (int mi = 0; mi < 2; mi++) {
            int mg = m0 + wm*32 + mi*16 + lq;
            {
                float zl = acc[mi][ni][0] + bL;
                float zr_ = acc[mi][ni][1] + bR;
                float sv = zl * (1.0f/(1.0f + expf(-zr_))) + g_x[(size_t)mg*HH + oc];
                g_s[(size_t)mg*HH + oc] = sv;
            }
            {
                int mg2 = mg + 8;
                float zl = acc[mi][ni][2] + bL;
                float zr_ = acc[mi][ni][3] + bR;
                float sv = zl * (1.0f/(1.0f + expf(-zr_))) + g_x[(size_t)mg2*HH + oc];
                g_s[(size_t)mg2*HH + oc] = sv;
            }
        }
    }
}

// ---------------------------------------------------------------------------
// LayerNorm, warp-per-row (float4), fused softplus heads on last layer.
// ---------------------------------------------------------------------------
__device__ __forceinline__ float softplus_f(float x) {
    return fmaxf(x, 0.f) + log1pf(expf(-fabsf(x)));
}

__global__ void __launch_bounds__(256) ln_kernel(
    const float* __restrict__ lng, const float* __restrict__ lnb,
    const float* __restrict__ mu_w, const float* __restrict__ mu_b,
    const float* __restrict__ al_w, const float* __restrict__ al_b,
    float* __restrict__ out, int half, int do_head)
{
    const int w = threadIdx.x >> 5, lane = threadIdx.x & 31;
    const int row = blockIdx.x*8 + w;
    const float4* sp = (const float4*)(g_s + (size_t)row*HH);
    float4 v0 = sp[lane];
    float4 v1 = sp[lane + 32];

    float s1 = v0.x+v0.y+v0.z+v0.w + v1.x+v1.y+v1.z+v1.w;
    float s2 = v0.x*v0.x+v0.y*v0.y+v0.z*v0.z+v0.w*v0.w
             + v1.x*v1.x+v1.y*v1.y+v1.z*v1.z+v1.w*v1.w;
    #pragma unroll
    for (int o = 16; o > 0; o >>= 1) {
        s1 += __shfl_xor_sync(0xffffffffu, s1, o);
        s2 += __shfl_xor_sync(0xffffffffu, s2, o);
    }
    float mean = s1 * (1.0f/HH);
    float var  = s2 * (1.0f/HH) - mean*mean;
    float inv  = rsqrtf(var + 1e-5f);

    const float4* gp = (const float4*)lng;
    const float4* bp = (const float4*)lnb;
    float4 g0 = gp[lane], g1 = gp[lane+32];
    float4 b0 = bp[lane], b1 = bp[lane+32];
    float4 y0, y1;
    y0.x = (v0.x-mean)*inv*g0.x + b0.x;  y0.y = (v0.y-mean)*inv*g0.y + b0.y;
    y0.z = (v0.z-mean)*inv*g0.z + b0.z;  y0.w = (v0.w-mean)*inv*g0.w + b0.w;
    y1.x = (v1.x-mean)*inv*g1.x + b1.x;  y1.y = (v1.y-mean)*inv*g1.y + b1.y;
    y1.z = (v1.z-mean)*inv*g1.z + b1.z;  y1.w = (v1.w-mean)*inv*g1.w + b1.w;

    float4* xp = (float4*)(g_x + (size_t)row*HH);
    xp[lane] = y0;
    xp[lane + 32] = y1;

    if (do_head) {
        const float4* mp = (const float4*)mu_w;
        const float4* ap = (const float4*)al_w;
        float4 m0 = mp[lane], m1 = mp[lane+32];
        float4 a0 = ap[lane], a1 = ap[lane+32];
        float sm = y0.x*m0.x + y0.y*m0.y + y0.z*m0.z + y0.w*m0.w
                 + y1.x*m1.x + y1.y*m1.y + y1.z*m1.z + y1.w*m1.w;
        float sa = y0.x*a0.x + y0.y*a0.y + y0.z*a0.z + y0.w*a0.w
                 + y1.x*a1.x + y1.y*a1.y + y1.z*a1.z + y1.w*a1.w;
        #pragma unroll
        for (int o = 16; o > 0; o >>= 1) {
            sm += __shfl_xor_sync(0xffffffffu, sm, o);
            sa += __shfl_xor_sync(0xffffffffu, sa, o);
        }
        if (lane == 0) {
            out[row]        = softplus_f(sm + mu_b[0]);
            out[half + row] = softplus_f(sa + al_b[0]);
        }
    }
}

// ---------------------------------------------------------------------------
extern "C" void kernel_launch(void* const* d_in, const int* in_sizes, int n_in,
                              void* d_out, int out_size)
{
    const float* x      = (const float*)d_in[0];
    const float* enc_w  = (const float*)d_in[1];
    const float* enc_b  = (const float*)d_in[2];
    const float* log_dt = (const float*)d_in[3];
    const float* logA   = (const float*)d_in[4];
    const float* A_im   = (const float*)d_in[5];
    const float* C_re   = (const float*)d_in[6];
    const float* C_im   = (const float*)d_in[7];
    const float* Dp     = (const float*)d_in[8];
    const float* out_w  = (const float*)d_in[9];
    const float* out_b  = (const float*)d_in[10];
    const float* ln_g   = (const float*)d_in[11];
    const float* ln_b   = (const float*)d_in[12];
    const float* mu_w   = (const float*)d_in[13];
    const float* mu_b   = (const float*)d_in[14];
    const float* al_w   = (const float*)d_in[15];
    const float* al_b   = (const float*)d_in[16];
    float* out = (float*)d_out;

    enc_kernel<<<GM, HH>>>(x, enc_w, enc_b);
    wconv_kernel<<<(NLAYERS*GN*GK)/256, 256>>>(out_w);

    for (int l = 0; l < NLAYERS; l++) {
        const float* ldt = log_dt + l*HH;
        const float* lA  = logA   + (size_t)l*HH*NN;
        const float* Ai  = A_im   + (size_t)l*HH*NN;
        scan1_kernel<<<dim3(HH/16, BB, NC), 128>>>(ldt, lA, Ai);
        scanfix_kernel<<<(BB*HH*NN)/256, 256>>>(ldt, lA, Ai);
        scan2_kernel<<<dim3(HH/16, BB, NC), 128>>>(
            ldt, lA, Ai,
            C_re + (size_t)l*HH*NN,
            C_im + (size_t)l*HH*NN,
            Dp   + l*HH);
        gemm_glu_kernel<<<dim3(8, GM/128), 256>>>(l, out_b + (size_t)l*GN);
        ln_kernel<<<GM/8, 256>>>(ln_g + l*HH, ln_b + l*HH,
                                 mu_w, mu_b, al_w, al_b,
                                 out, out_size/2, (l == NLAYERS-1) ? 1 : 0);
    }
}

// round 5
// speedup vs baseline: 2.1299x; 1.3821x over previous
#include <cuda_runtime.h>
#include <cuda_bf16.h>
#include <math.h>

// Problem constants
#define BB 16
#define LL 2048
#define DIN 8
#define HH 256
#define NN 64
#define NLAYERS 4
#define GM (BB*LL)      // 32768 rows
#define GK HH           // 256
#define GN (2*HH)       // 512
#define NC 16           // time chunks
#define TT (LL/NC)      // 128
#define MM (BB*NC)      // 256 chunk-columns

typedef unsigned long long ull;
typedef unsigned int u32;

// Scratch (device globals)
__device__ float g_x[(size_t)GM*HH];                    // activations (row,h)
__device__ float g_s[(size_t)GM*HH];                    // pre-LN (row,h)
__device__ __nv_bfloat16 g_gh[(size_t)GM*HH];           // gelu out hi (row,h)
__device__ __nv_bfloat16 g_gl[(size_t)GM*HH];           // gelu out lo
__device__ __nv_bfloat16 g_wh[(size_t)NLAYERS*GN*GK];   // GLU W hi
__device__ __nv_bfloat16 g_wl[(size_t)NLAYERS*GN*GK];   // GLU W lo
__device__ __nv_bfloat16 g_Xh[(size_t)HH*MM*256];       // X=[u;z0] hi  (h,m,k)
__device__ __nv_bfloat16 g_Xl[(size_t)HH*MM*256];       // X lo
__device__ __nv_bfloat16 g_GAh[(size_t)HH*128*256];     // [K|V] hi (h,r,k)
__device__ __nv_bfloat16 g_GAl[(size_t)HH*128*256];
__device__ __nv_bfloat16 g_GWh[(size_t)HH*128*128];     // W hi (h,i,s)
__device__ __nv_bfloat16 g_GWl[(size_t)HH*128*128];
__device__ float g_zc[(size_t)HH*128*MM];               // Zend0 (h,i,m)
__device__ float g_y[(size_t)HH*TT*MM];                 // conv out (h,t,m)

__device__ __forceinline__ void bsplit(float v, __nv_bfloat16& h, __nv_bfloat16& l) {
    h = __float2bfloat16_rn(v);
    l = __float2bfloat16_rn(v - __bfloat162float(h));
}

// ---------------------------------------------------------------------------
// Encoder (row,h)
// ---------------------------------------------------------------------------
__global__ void enc_kernel(const float* __restrict__ x,
                           const float* __restrict__ w,
                           const float* __restrict__ b)
{
    int row = blockIdx.x;
    int h = threadIdx.x;
    __shared__ float xr[DIN];
    if (h < DIN) xr[h] = x[row*DIN + h];
    __syncthreads();
    float s = b[h];
    #pragma unroll
    for (int k = 0; k < DIN; k++)
        s = fmaf(xr[k], w[h*DIN + k], s);
    g_x[(size_t)row*HH + h] = s;
}

// ---------------------------------------------------------------------------
// One-shot GLU W -> bf16 hi/lo split
// ---------------------------------------------------------------------------
__global__ void wconv_kernel(const float* __restrict__ W)
{
    size_t i = (size_t)blockIdx.x*256 + threadIdx.x;
    float w = W[i];
    bsplit(w, g_wh[i], g_wl[i]);
}

// ---------------------------------------------------------------------------
__device__ __forceinline__ void s4_lambda(
    const float* log_dt, const float* logA_re, const float* A_im,
    int h, int n, float& Lr, float& Li, float& are, float& aim)
{
    float dt = expf(log_dt[h]);
    are = -expf(logA_re[h*NN + n]);
    aim = A_im[h*NN + n];
    float er = expf(dt*are);
    float dim = dt*aim;
    Lr = er*cosf(dim);
    Li = er*sinf(dim);
}

// ---------------------------------------------------------------------------
// fwdT: g_x (row,h) fp32 -> X (h, m, t) bf16 hi/lo  (k-cols 0..127)
//   grid (m=256, hc=8), block 256
// ---------------------------------------------------------------------------
__global__ void __launch_bounds__(256) fwdT_kernel()
{
    const int m = blockIdx.x, h0 = blockIdx.y*32;
    const int b = m >> 4, c = m & 15;
    const size_t rbase = ((size_t)b*LL + c*TT)*HH;
    __shared__ float sT[128][33];
    const int tid = threadIdx.x;
    const int hl = (tid & 7)*4, tr0 = tid >> 3;
    #pragma unroll
    for (int p = 0; p < 4; p++) {
        int tt = p*32 + tr0;
        float4 v = *(const float4*)(g_x + rbase + (size_t)tt*HH + h0 + hl);
        sT[tt][hl] = v.x; sT[tt][hl+1] = v.y; sT[tt][hl+2] = v.z; sT[tt][hl+3] = v.w;
    }
    __syncthreads();
    const int w = tid >> 5, lane = tid & 31;
    union P4 { __nv_bfloat16 b[4]; ull u; };
    #pragma unroll
    for (int p = 0; p < 4; p++) {
        int hh = p*8 + w;             // 0..31
        int t0 = lane*4;
        P4 ph, pl;
        #pragma unroll
        for (int i = 0; i < 4; i++) bsplit(sT[t0+i][hh], ph.b[i], pl.b[i]);
        size_t dst = (size_t)(h0+hh)*((size_t)MM*256) + (size_t)m*256 + t0;
        *(ull*)(g_Xh + dst) = ph.u;
        *(ull*)(g_Xl + dst) = pl.u;
    }
}

// ---------------------------------------------------------------------------
// genG: per-channel G_A=[K|V] (128x256), G_W (128x128), bf16 hi/lo.
//   grid H, block 128.
// ---------------------------------------------------------------------------
__global__ void __launch_bounds__(128) genG_kernel(
    const float* __restrict__ log_dt,
    const float* __restrict__ logA_re,
    const float* __restrict__ A_im,
    const float* __restrict__ C_re,
    const float* __restrict__ C_im,
    const float* __restrict__ Dp)
{
    const int h = blockIdx.x;
    const int t = threadIdx.x;
    __shared__ float s_cr[64], s_ci[64], s_lr[64], s_li[64];
    __shared__ float s_pr[64][33], s_pi[64][33];
    __shared__ float s_k[128];

    float pr = 1.f, pi = 0.f;
    if (t < 64) {
        float are, aim, Lr, Li;
        s4_lambda(log_dt, logA_re, A_im, h, t, Lr, Li, are, aim);
        s_lr[t] = Lr; s_li[t] = Li;
        float Cre = C_re[h*NN + t], Cim = C_im[h*NN + t];
        float nr = Lr - 1.f, ni = Li;
        float tr = Cre*nr - Cim*ni, ti = Cre*ni + Cim*nr;
        float inv = 2.f/(are*are + aim*aim);
        s_cr[t] =  inv*(tr*are + ti*aim);
        s_ci[t] = -inv*(ti*are - tr*aim);
    }
    __syncthreads();
    const float Dh = Dp[h];
    __nv_bfloat16* GAh = g_GAh + (size_t)h*128*256;
    __nv_bfloat16* GAl = g_GAl + (size_t)h*128*256;
    __nv_bfloat16* GWh = g_GWh + (size_t)h*128*128;
    __nv_bfloat16* GWl = g_GWl + (size_t)h*128*128;

    for (int cd = 0; cd < 4; cd++) {
        if (t < 64) {
            float Lr = s_lr[t], Li = s_li[t];
            #pragma unroll
            for (int dd = 0; dd < 32; dd++) {
                s_pr[t][dd] = pr; s_pi[t][dd] = pi;
                float npr = pr*Lr - pi*Li;
                float npi = pr*Li + pi*Lr;
                pr = npr; pi = npi;
            }
        }
        __syncthreads();
        // k[d] partials: d = cd*32 + (t>>2), quarter t&3 over 16 n's
        {
            int dd = t >> 2, q = t & 3;
            float part = 0.f;
            for (int n = q*16; n < q*16 + 16; n++)
                part += s_cr[n]*s_pr[n][dd] + s_ci[n]*s_pi[n][dd];
            part += __shfl_xor_sync(0xffffffffu, part, 1);
            part += __shfl_xor_sync(0xffffffffu, part, 2);
            int d = cd*32 + dd;
            if (q == 0) s_k[d] = part + (d == 0 ? Dh : 0.f);
        }
        // V rows r=d-1 (cols 128..255)
        for (int dd = 0; dd < 32; dd++) {
            int d = cd*32 + dd, r = d - 1;
            if (r >= 0) {
                float v;
                if (t < 64)
                    v = s_cr[t]*s_pr[t][dd] + s_ci[t]*s_pi[t][dd];
                else {
                    int j = t - 64;
                    v = s_ci[j]*s_pr[j][dd] - s_cr[j]*s_pi[j][dd];
                }
                __nv_bfloat16 hb, lb; bsplit(v, hb, lb);
                GAh[r*256 + 128 + t] = hb;
                GAl[r*256 + 128 + t] = lb;
            }
        }
        // W rows: row<64 -> Re(lambda_row^{127-s}), row>=64 -> Im
        for (int p = 0; p < 32; p++) {
            int row = p*4 + (t >> 5);
            int sc = t & 31;
            int s = 96 - cd*32 + sc;
            int dd = 31 - sc;
            float v = (row < 64) ? s_pr[row][dd] : s_pi[row-64][dd];
            __nv_bfloat16 hb, lb; bsplit(v, hb, lb);
            GWh[row*128 + s] = hb;
            GWl[row*128 + s] = lb;
        }
        __syncthreads();
    }
    // V row r=127 (d=128, from final pr/pi)
    if (t < 64) { s_pr[t][0] = pr; s_pi[t][0] = pi; }
    __syncthreads();
    {
        float v;
        if (t < 64)
            v = s_cr[t]*s_pr[t][0] + s_ci[t]*s_pi[t][0];
        else {
            int j = t - 64;
            v = s_ci[j]*s_pr[j][0] - s_cr[j]*s_pi[j][0];
        }
        __nv_bfloat16 hb, lb; bsplit(v, hb, lb);
        GAh[127*256 + 128 + t] = hb;
        GAl[127*256 + 128 + t] = lb;
    }
    // Toeplitz region (cols 0..127)
    for (int r = 0; r < 128; r++) {
        float v = (t <= r) ? s_k[r - t] : 0.f;
        __nv_bfloat16 hb, lb; bsplit(v, hb, lb);
        GAh[r*256 + t] = hb;
        GAl[r*256 + t] = lb;
    }
}

// ---------------------------------------------------------------------------
// scanfix: compose Zend0 across chunks; write z0 (bf16 hi/lo) into X rows 128+
// ---------------------------------------------------------------------------
__global__ void __launch_bounds__(256) scanfix_kernel(
    const float* __restrict__ log_dt,
    const float* __restrict__ logA_re,
    const float* __restrict__ A_im)
{
    int gid = blockIdx.x*256 + threadIdx.x;     // < BB*HH*NN
    int n = gid & 63, h = (gid >> 6) & 255, b = gid >> 14;

    float Lr, Li, are, aim;
    s4_lambda(log_dt, logA_re, A_im, h, n, Lr, Li, are, aim);
    #pragma unroll
    for (int s = 0; s < 7; s++) {       // lambda^128
        float nr = Lr*Lr - Li*Li, ni = 2.f*Lr*Li;
        Lr = nr; Li = ni;
    }

    const float* zcre = g_zc + (size_t)h*128*MM + n*MM;
    const float* zcim = zcre + 64*MM;
    __nv_bfloat16* Xh = g_Xh + (size_t)h*MM*256;
    __nv_bfloat16* Xl = g_Xl + (size_t)h*MM*256;

    float cr = 0.f, ci = 0.f;
    #pragma unroll
    for (int c = 0; c < NC; c++) {
        int m = b*16 + c;
        __nv_bfloat16 hb, lb;
        bsplit(cr, hb, lb);
        Xh[(size_t)m*256 + 128 + n] = hb; Xl[(size_t)m*256 + 128 + n] = lb;
        bsplit(ci, hb, lb);
        Xh[(size_t)m*256 + 192 + n] = hb; Xl[(size_t)m*256 + 192 + n] = lb;
        float zr = zcre[m], zi = zcim[m];
        float nr = Lr*cr - Li*ci + zr;
        float ni = Lr*ci + Li*cr + zi;
        cr = nr; ci = ni;
    }
}

// ---------------------------------------------------------------------------
// gemm_s4: per-channel bf16x3 GEMM (pass 1: Zend0 = G_W * U;  pass 2: Y = G_A * X)
//   grid (4 m-tiles, H), block 256. 8 warps = 4 row-quarters x 2 m-halves.
// ---------------------------------------------------------------------------
__device__ __forceinline__ void cp16(u32 dst, const void* src) {
    asm volatile("cp.async.cg.shared.global [%0], [%1], 16;" :: "r"(dst), "l"(src));
}
__device__ __forceinline__ void ldsm4(u32& r0, u32& r1, u32& r2, u32& r3, u32 addr) {
    asm volatile("ldmatrix.sync.aligned.m8n8.x4.shared.b16 {%0,%1,%2,%3},[%4];"
                 : "=r"(r0), "=r"(r1), "=r"(r2), "=r"(r3) : "r"(addr));
}
__device__ __forceinline__ void mma_bf16(float* d, const u32* a, const u32* b) {
    asm volatile(
        "mma.sync.aligned.m16n8k16.row.col.f32.bf16.bf16.f32 "
        "{%0,%1,%2,%3},{%4,%5,%6,%7},{%8,%9},{%0,%1,%2,%3};"
        : "+f"(d[0]), "+f"(d[1]), "+f"(d[2]), "+f"(d[3])
        : "r"(a[0]), "r"(a[1]), "r"(a[2]), "r"(a[3]), "r"(b[0]), "r"(b[1]));
}

#define SSTG 12288   // per-stage: A 8KB + B 4KB

__global__ void __launch_bounds__(256) gemm_s4_kernel(int pass)
{
    __shared__ __align__(128) char smem_buf[3*SSTG];
    const int h  = blockIdx.y;
    const int mt = blockIdx.x;
    const int tid = threadIdx.x, lane = tid & 31, w = tid >> 5;
    const int wm = w & 3, wn = w >> 2;

    const int NK = (pass == 1) ? 128 : 256;
    const __nv_bfloat16* Ah = (pass == 1) ? g_GWh + (size_t)h*128*128
                                          : g_GAh + (size_t)h*128*256;
    const __nv_bfloat16* Al = (pass == 1) ? g_GWl + (size_t)h*128*128
                                          : g_GAl + (size_t)h*128*256;
    const __nv_bfloat16* Bh = g_Xh + (size_t)h*MM*256;
    const __nv_bfloat16* Bl = g_Xl + (size_t)h*MM*256;
    float* outp = ((pass == 1) ? g_zc : g_y) + (size_t)h*128*MM;

    const int ckr = NK/32;        // chunks per region
    const int nch = 3*ckr;
    const u32 smem_base = (u32)__cvta_generic_to_shared(smem_buf);

    float acc[2][4][4];
    #pragma unroll
    for (int mi = 0; mi < 2; mi++)
        #pragma unroll
        for (int ni = 0; ni < 4; ni++)
            #pragma unroll
            for (int r = 0; r < 4; r++) acc[mi][ni][r] = 0.f;

    auto load_chunk = [&](int kc, int stage) {
        int region = kc / ckr;
        int k0 = (kc - region*ckr) * 32;
        const __nv_bfloat16* As = (region == 1) ? Al : Ah;
        const __nv_bfloat16* Bs = (region == 2) ? Bl : Bh;
        u32 abase = smem_base + stage*SSTG;
        u32 bbase = abase + 8192;
        #pragma unroll
        for (int i = 0; i < 2; i++) {
            int gid = i*256 + tid;
            int row = gid >> 2, g = gid & 3;
            int pg = g ^ ((row >> 1) & 3);
            cp16(abase + row*64 + pg*16, As + (size_t)row*NK + k0 + g*8);
        }
        {
            int row = tid >> 2, g = tid & 3;
            int pg = g ^ ((row >> 1) & 3);
            cp16(bbase + row*64 + pg*16, Bs + (size_t)(mt*64 + row)*256 + k0 + g*8);
        }
    };

    load_chunk(0, 0);
    asm volatile("cp.async.commit_group;");
    load_chunk(1, 1);
    asm volatile("cp.async.commit_group;");

    for (int kc = 0; kc < nch; kc++) {
        if (kc + 2 < nch) load_chunk(kc + 2, (kc + 2) % 3);
        asm volatile("cp.async.commit_group;");
        asm volatile("cp.async.wait_group 2;");
        __syncthreads();

        const int stage = kc % 3;
        const u32 abase = smem_base + stage*SSTG;
        const u32 bbase = abase + 8192;

        #pragma unroll
        for (int ks = 0; ks < 2; ks++) {
            const int grp = lane >> 3, rh = lane & 7;
            u32 a[2][4];
            #pragma unroll
            for (int mi = 0; mi < 2; mi++) {
                int row = wm*32 + mi*16 + rh + (grp & 1)*8;
                int kg  = 2*ks + (grp >> 1);
                u32 addr = abase + row*64 + ((kg ^ ((row >> 1) & 3))*16);
                ldsm4(a[mi][0], a[mi][1], a[mi][2], a[mi][3], addr);
            }
            u32 bfr[4][2];
            #pragma unroll
            for (int nf = 0; nf < 2; nf++) {
                int row = wn*32 + nf*16 + rh + (grp >> 1)*8;
                int kg  = 2*ks + (grp & 1);
                u32 addr = bbase + row*64 + ((kg ^ ((row >> 1) & 3))*16);
                u32 r0, r1, r2, r3;
                ldsm4(r0, r1, r2, r3, addr);
                bfr[nf*2][0] = r0; bfr[nf*2][1] = r1;
                bfr[nf*2+1][0] = r2; bfr[nf*2+1][1] = r3;
            }
            #pragma unroll
            for (int mi = 0; mi < 2; mi++)
                #pragma unroll
                for (int ni = 0; ni < 4; ni++)
                    mma_bf16(acc[mi][ni], a[mi], bfr[ni]);
        }
        __syncthreads();
    }

    const int lq = lane >> 2, lc = lane & 3;
    #pragma unroll
    for (int mi = 0; mi < 2; mi++) {
        #pragma unroll
        for (int ni = 0; ni < 4; ni++) {
            int row = wm*32 + mi*16 + lq;
            int col = mt*64 + wn*32 + ni*8 + lc*2;
            float2 v0; v0.x = acc[mi][ni][0]; v0.y = acc[mi][ni][1];
            float2 v1; v1.x = acc[mi][ni][2]; v1.y = acc[mi][ni][3];
            *(float2*)(outp + (size_t)row*MM + col) = v0;
            *(float2*)(outp + (size_t)(row+8)*MM + col) = v1;
        }
    }
}

// ---------------------------------------------------------------------------
// backT: g_y (h,t,m) fp32 -> gelu -> g_gh/g_gl (row,h) bf16 hi/lo
//   grid (m/32, t/8, h/32), block 256
// ---------------------------------------------------------------------------
__global__ void __launch_bounds__(256) backT_kernel()
{
    const int m0 = blockIdx.x*32, t0 = blockIdx.y*8, h0 = blockIdx.z*32;
    __shared__ float sB[256][33];     // [t*32+m][h]
    const int tid = threadIdx.x, w = tid >> 5, lane = tid & 31;

    for (int i = 0; i < 32; i++) {
        int seg = w*32 + i;            // 0..255
        int hh = seg >> 3, tt = seg & 7;
        float v = g_y[(size_t)(h0+hh)*TT*MM + (size_t)(t0+tt)*MM + m0 + lane];
        sB[tt*32 + lane][hh] = v;
    }
    __syncthreads();
    for (int i = 0; i < 32; i++) {
        int pair = w*32 + i;
        int mm = pair >> 3, tt = pair & 7;
        int m = m0 + mm;
        int b = m >> 4, cc = m & 15;
        size_t row = (size_t)b*LL + cc*TT + t0 + tt;
        float yv = sB[tt*32 + mm][lane];
        float gv = 0.5f*yv*(1.0f + erff(yv*0.70710678118654752f));
        __nv_bfloat16 hb, lb; bsplit(gv, hb, lb);
        g_gh[row*HH + h0 + lane] = hb;
        g_gl[row*HH + h0 + lane] = lb;
    }
}

// ---------------------------------------------------------------------------
// GLU GEMM (unchanged from R4): bf16x3, fused GLU+bias+residual
// ---------------------------------------------------------------------------
#define NCHUNK 24
__global__ void __launch_bounds__(256) gemm_glu_kernel(int l, const float* __restrict__ bias)
{
    __shared__ __align__(128) char smem_buf[3*SSTG];

    const int m0  = blockIdx.y * 128;
    const int nb  = blockIdx.x;
    const int tid = threadIdx.x;
    const int lane = tid & 31, w = tid >> 5;
    const int wm = w & 3;
    const int wn = w >> 2;

    const __nv_bfloat16* Wh = g_wh + (size_t)l*GN*GK;
    const __nv_bfloat16* Wl = g_wl + (size_t)l*GN*GK;

    const u32 smem_base = (u32)__cvta_generic_to_shared(smem_buf);

    float acc[2][4][4];
    #pragma unroll
    for (int mi = 0; mi < 2; mi++)
        #pragma unroll
        for (int ni = 0; ni < 4; ni++)
            #pragma unroll
            for (int r = 0; r < 4; r++) acc[mi][ni][r] = 0.f;

    auto load_chunk = [&](int kc, int stage) {
        int region = kc >> 3;
        int k0 = (kc & 7) * 32;
        const __nv_bfloat16* Asrc = (region == 1) ? g_gl : g_gh;
        const __nv_bfloat16* Bsrc = (region == 2) ? Wl : Wh;
        u32 abase = smem_base + stage*SSTG;
        u32 bbase = abase + 8192;
        #pragma unroll
        for (int i = 0; i < 2; i++) {
            int gid = i*256 + tid;
            int row = gid >> 2, g = gid & 3;
            int pg = g ^ ((row >> 1) & 3);
            cp16(abase + row*64 + pg*16, Asrc + (size_t)(m0 + row)*GK + k0 + g*8);
        }
        {
            int row = tid >> 2, g = tid & 3;
            int pg = g ^ ((row >> 1) & 3);
            int wr = nb*32 + (row >> 1) + (row & 1)*256;
            cp16(bbase + row*64 + pg*16, Bsrc + (size_t)wr*GK + k0 + g*8);
        }
    };

    load_chunk(0, 0);
    asm volatile("cp.async.commit_group;");
    load_chunk(1, 1);
    asm volatile("cp.async.commit_group;");

    for (int kc = 0; kc < NCHUNK; kc++) {
        if (kc + 2 < NCHUNK) load_chunk(kc + 2, (kc + 2) % 3);
        asm volatile("cp.async.commit_group;");
        asm volatile("cp.async.wait_group 2;");
        __syncthreads();

        const int stage = kc % 3;
        const u32 abase = smem_base + stage*SSTG;
        const u32 bbase = abase + 8192;

        #pragma unroll
        for (int ks = 0; ks < 2; ks++) {
            const int grp = lane >> 3, rh = lane & 7;
            u32 a[2][4];
            #pragma unroll
            for (int mi = 0; mi < 2; mi++) {
                int row = wm*32 + mi*16 + rh + (grp & 1)*8;
                int kg  = 2*ks + (grp >> 1);
                u32 addr = abase + row*64 + ((kg ^ ((row >> 1) & 3))*16);
                ldsm4(a[mi][0], a[mi][1], a[mi][2], a[mi][3], addr);
            }
            u32 bfr[4][2];
            #pragma unroll
            for (int nf = 0; nf < 2; nf++) {
                int row = wn*32 + nf*16 + rh + (grp >> 1)*8;
                int kg  = 2*ks + (grp & 1);
                u32 addr = bbase + row*64 + ((kg ^ ((row >> 1) & 3))*16);
                u32 r0, r1, r2, r3;
                ldsm4(r0, r1, r2, r3, addr);
                bfr[nf*2][0] = r0; bfr[nf*2][1] = r1;
                bfr[nf*2+1][0] = r2; bfr[nf*2+1][1] = r3;
            }
            #pragma unroll
            for (int mi = 0; mi < 2; mi++)
                #pragma unroll
                for (int ni = 0; ni < 4; ni++)
                    mma_bf16(acc[mi][ni], a[mi], bfr[ni]);
        }
        __syncthreads();
    }

    const int lc = lane & 3, lq = lane >> 2;
    #pragma unroll
    for (int ni = 0; ni < 4; ni++) {
        const int oc = nb*32 + wn*16 + ni*4 + lc;
        const float bL = bias[oc];
        const float bR = bias[oc + 256];
        #pragma unroll
        for (int mi = 0; mi < 2; mi++) {
            int mg = m0 + wm*32 + mi*16 + lq;
            {
                float zl = acc[mi][ni][0] + bL;
                float zr_ = acc[mi][ni][1] + bR;
                float sv = zl * (1.0f/(1.0f + expf(-zr_))) + g_x[(size_t)mg*HH + oc];
                g_s[(size_t)mg*HH + oc] = sv;
            }
            {
                int mg2 = mg + 8;
                float zl = acc[mi][ni][2] + bL;
                float zr_ = acc[mi][ni][3] + bR;
                float sv = zl * (1.0f/(1.0f + expf(-zr_))) + g_x[(size_t)mg2*HH + oc];
                g_s[(size_t)mg2*HH + oc] = sv;
            }
        }
    }
}

// ---------------------------------------------------------------------------
// LayerNorm warp-per-row + fused heads on last layer
// ---------------------------------------------------------------------------
__device__ __forceinline__ float softplus_f(float x) {
    return fmaxf(x, 0.f) + log1pf(expf(-fabsf(x)));
}

__global__ void __launch_bounds__(256) ln_kernel(
    const float* __restrict__ lng, const float* __restrict__ lnb,
    const float* __restrict__ mu_w, const float* __restrict__ mu_b,
    const float* __restrict__ al_w, const float* __restrict__ al_b,
    float* __restrict__ out, int half, int do_head)
{
    const int w = threadIdx.x >> 5, lane = threadIdx.x & 31;
    const int row = blockIdx.x*8 + w;
    const float4* sp = (const float4*)(g_s + (size_t)row*HH);
    float4 v0 = sp[lane];
    float4 v1 = sp[lane + 32];

    float s1 = v0.x+v0.y+v0.z+v0.w + v1.x+v1.y+v1.z+v1.w;
    float s2 = v0.x*v0.x+v0.y*v0.y+v0.z*v0.z+v0.w*v0.w
             + v1.x*v1.x+v1.y*v1.y+v1.z*v1.z+v1.w*v1.w;
    #pragma unroll
    for (int o = 16; o > 0; o >>= 1) {
        s1 += __shfl_xor_sync(0xffffffffu, s1, o);
        s2 += __shfl_xor_sync(0xffffffffu, s2, o);
    }
    float mean = s1 * (1.0f/HH);
    float var  = s2 * (1.0f/HH) - mean*mean;
    float inv  = rsqrtf(var + 1e-5f);

    const float4* gp = (const float4*)lng;
    const float4* bp = (const float4*)lnb;
    float4 g0 = gp[lane], g1 = gp[lane+32];
    float4 b0 = bp[lane], b1 = bp[lane+32];
    float4 y0, y1;
    y0.x = (v0.x-mean)*inv*g0.x + b0.x;  y0.y = (v0.y-mean)*inv*g0.y + b0.y;
    y0.z = (v0.z-mean)*inv*g0.z + b0.z;  y0.w = (v0.w-mean)*inv*g0.w + b0.w;
    y1.x = (v1.x-mean)*inv*g1.x + b1.x;  y1.y = (v1.y-mean)*inv*g1.y + b1.y;
    y1.z = (v1.z-mean)*inv*g1.z + b1.z;  y1.w = (v1.w-mean)*inv*g1.w + b1.w;

    float4* xp = (float4*)(g_x + (size_t)row*HH);
    xp[lane] = y0;
    xp[lane + 32] = y1;

    if (do_head) {
        const float4* mp = (const float4*)mu_w;
        const float4* ap = (const float4*)al_w;
        float4 m0 = mp[lane], m1 = mp[lane+32];
        float4 a0 = ap[lane], a1 = ap[lane+32];
        float sm = y0.x*m0.x + y0.y*m0.y + y0.z*m0.z + y0.w*m0.w
                 + y1.x*m1.x + y1.y*m1.y + y1.z*m1.z + y1.w*m1.w;
        float sa = y0.x*a0.x + y0.y*a0.y + y0.z*a0.z + y0.w*a0.w
                 + y1.x*a1.x + y1.y*a1.y + y1.z*a1.z + y1.w*a1.w;
        #pragma unroll
        for (int o = 16; o > 0; o >>= 1) {
            sm += __shfl_xor_sync(0xffffffffu, sm, o);
            sa += __shfl_xor_sync(0xffffffffu, sa, o);
        }
        if (lane == 0) {
            out[row]        = softplus_f(sm + mu_b[0]);
            out[half + row] = softplus_f(sa + al_b[0]);
        }
    }
}

// ---------------------------------------------------------------------------
extern "C" void kernel_launch(void* const* d_in, const int* in_sizes, int n_in,
                              void* d_out, int out_size)
{
    const float* x      = (const float*)d_in[0];
    const float* enc_w  = (const float*)d_in[1];
    const float* enc_b  = (const float*)d_in[2];
    const float* log_dt = (const float*)d_in[3];
    const float* logA   = (const float*)d_in[4];
    const float* A_im   = (const float*)d_in[5];
    const float* C_re   = (const float*)d_in[6];
    const float* C_im   = (const float*)d_in[7];
    const float* Dp     = (const float*)d_in[8];
    const float* out_w  = (const float*)d_in[9];
    const float* out_b  = (const float*)d_in[10];
    const float* ln_g   = (const float*)d_in[11];
    const float* ln_b   = (const float*)d_in[12];
    const float* mu_w   = (const float*)d_in[13];
    const float* mu_b   = (const float*)d_in[14];
    const float* al_w   = (const float*)d_in[15];
    const float* al_b   = (const float*)d_in[16];
    float* out = (float*)d_out;

    enc_kernel<<<GM, HH>>>(x, enc_w, enc_b);
    wconv_kernel<<<(NLAYERS*GN*GK)/256, 256>>>(out_w);

    for (int l = 0; l < NLAYERS; l++) {
        const float* ldt = log_dt + l*HH;
        const float* lA  = logA   + (size_t)l*HH*NN;
        const float* Ai  = A_im   + (size_t)l*HH*NN;

        fwdT_kernel<<<dim3(MM, 8), 256>>>();
        genG_kernel<<<HH, 128>>>(ldt, lA, Ai,
                                 C_re + (size_t)l*HH*NN,
                                 C_im + (size_t)l*HH*NN,
                                 Dp + l*HH);
        gemm_s4_kernel<<<dim3(4, HH), 256>>>(1);
        scanfix_kernel<<<(BB*HH*NN)/256, 256>>>(ldt, lA, Ai);
        gemm_s4_kernel<<<dim3(4, HH), 256>>>(2);
        backT_kernel<<<dim3(MM/32, TT/8, HH/32), 256>>>();
        gemm_glu_kernel<<<dim3(8, GM/128), 256>>>(l, out_b + (size_t)l*GN);
        ln_kernel<<<GM/8, 256>>>(ln_g + l*HH, ln_b + l*HH,
                                 mu_w, mu_b, al_w, al_b,
                                 out, out_size/2, (l == NLAYERS-1) ? 1 : 0);
    }
}

// round 6
// speedup vs baseline: 2.4159x; 1.1343x over previous
#include <cuda_runtime.h>
#include <cuda_bf16.h>
#include <math.h>

// Problem constants
#define BB 16
#define LL 2048
#define DIN 8
#define HH 256
#define NN 64
#define NLAYERS 4
#define GM (BB*LL)      // 32768 rows
#define GK HH           // 256
#define GN (2*HH)       // 512
#define NC 16           // time chunks
#define TT (LL/NC)      // 128
#define MM (BB*NC)      // 256 chunk-columns

typedef unsigned long long ull;
typedef unsigned int u32;

// Scratch (device globals)
__device__ float g_x[(size_t)GM*HH];                    // activations (row,h)
__device__ float g_s[(size_t)GM*HH];                    // pre-LN (row,h)
__device__ __nv_bfloat16 g_gh[(size_t)GM*HH];           // gelu out hi (row,h)
__device__ __nv_bfloat16 g_gl[(size_t)GM*HH];           // gelu out lo
__device__ __nv_bfloat16 g_wh[(size_t)NLAYERS*GN*GK];   // GLU W hi
__device__ __nv_bfloat16 g_wl[(size_t)NLAYERS*GN*GK];   // GLU W lo
__device__ __nv_bfloat16 g_Xh[(size_t)HH*MM*256];       // X=[u;z0] hi  (h,m,k)
__device__ __nv_bfloat16 g_Xl[(size_t)HH*MM*256];       // X lo
__device__ __nv_bfloat16 g_GAh[(size_t)HH*128*256];     // [K|V] hi (h,r,k)
__device__ __nv_bfloat16 g_GAl[(size_t)HH*128*256];
__device__ __nv_bfloat16 g_GWh[(size_t)HH*128*128];     // W hi (h,i,s)
__device__ __nv_bfloat16 g_GWl[(size_t)HH*128*128];
__device__ float g_zc[(size_t)HH*128*MM];               // Zend0 (h,i,m)
__device__ float g_y[(size_t)HH*TT*MM];                 // conv out (h,t,m)

__device__ __forceinline__ void bsplit(float v, __nv_bfloat16& h, __nv_bfloat16& l) {
    h = __float2bfloat16_rn(v);
    l = __float2bfloat16_rn(v - __bfloat162float(h));
}

// ---------------------------------------------------------------------------
// Encoder (row,h)
// ---------------------------------------------------------------------------
__global__ void enc_kernel(const float* __restrict__ x,
                           const float* __restrict__ w,
                           const float* __restrict__ b)
{
    int row = blockIdx.x;
    int h = threadIdx.x;
    __shared__ float xr[DIN];
    if (h < DIN) xr[h] = x[row*DIN + h];
    __syncthreads();
    float s = b[h];
    #pragma unroll
    for (int k = 0; k < DIN; k++)
        s = fmaf(xr[k], w[h*DIN + k], s);
    g_x[(size_t)row*HH + h] = s;
}

// ---------------------------------------------------------------------------
// One-shot GLU W -> bf16 hi/lo split
// ---------------------------------------------------------------------------
__global__ void wconv_kernel(const float* __restrict__ W)
{
    size_t i = (size_t)blockIdx.x*256 + threadIdx.x;
    float w = W[i];
    bsplit(w, g_wh[i], g_wl[i]);
}

// ---------------------------------------------------------------------------
__device__ __forceinline__ void s4_lambda(
    const float* log_dt, const float* logA_re, const float* A_im,
    int h, int n, float& Lr, float& Li, float& are, float& aim)
{
    float dt = expf(log_dt[h]);
    are = -expf(logA_re[h*NN + n]);
    aim = A_im[h*NN + n];
    float er = expf(dt*are);
    float dim = dt*aim;
    Lr = er*cosf(dim);
    Li = er*sinf(dim);
}

// ---------------------------------------------------------------------------
// fwdT: g_x (row,h) fp32 -> X (h, m, t) bf16 hi/lo  (k-cols 0..127)
// ---------------------------------------------------------------------------
__global__ void __launch_bounds__(256) fwdT_kernel()
{
    const int m = blockIdx.x, h0 = blockIdx.y*32;
    const int b = m >> 4, c = m & 15;
    const size_t rbase = ((size_t)b*LL + c*TT)*HH;
    __shared__ float sT[128][33];
    const int tid = threadIdx.x;
    const int hl = (tid & 7)*4, tr0 = tid >> 3;
    #pragma unroll
    for (int p = 0; p < 4; p++) {
        int tt = p*32 + tr0;
        float4 v = *(const float4*)(g_x + rbase + (size_t)tt*HH + h0 + hl);
        sT[tt][hl] = v.x; sT[tt][hl+1] = v.y; sT[tt][hl+2] = v.z; sT[tt][hl+3] = v.w;
    }
    __syncthreads();
    const int w = tid >> 5, lane = tid & 31;
    union P4 { __nv_bfloat16 b[4]; ull u; };
    #pragma unroll
    for (int p = 0; p < 4; p++) {
        int hh = p*8 + w;
        int t0 = lane*4;
        P4 ph, pl;
        #pragma unroll
        for (int i = 0; i < 4; i++) bsplit(sT[t0+i][hh], ph.b[i], pl.b[i]);
        size_t dst = (size_t)(h0+hh)*((size_t)MM*256) + (size_t)m*256 + t0;
        *(ull*)(g_Xh + dst) = ph.u;
        *(ull*)(g_Xl + dst) = pl.u;
    }
}

// ---------------------------------------------------------------------------
// genG: per-channel G_A=[K|V] (128x256), G_W (128x128), bf16 hi/lo.
// ---------------------------------------------------------------------------
__global__ void __launch_bounds__(128) genG_kernel(
    const float* __restrict__ log_dt,
    const float* __restrict__ logA_re,
    const float* __restrict__ A_im,
    const float* __restrict__ C_re,
    const float* __restrict__ C_im,
    const float* __restrict__ Dp)
{
    const int h = blockIdx.x;
    const int t = threadIdx.x;
    __shared__ float s_cr[64], s_ci[64], s_lr[64], s_li[64];
    __shared__ float s_pr[64][33], s_pi[64][33];
    __shared__ float s_k[128];

    float pr = 1.f, pi = 0.f;
    if (t < 64) {
        float are, aim, Lr, Li;
        s4_lambda(log_dt, logA_re, A_im, h, t, Lr, Li, are, aim);
        s_lr[t] = Lr; s_li[t] = Li;
        float Cre = C_re[h*NN + t], Cim = C_im[h*NN + t];
        float nr = Lr - 1.f, ni = Li;
        float tr = Cre*nr - Cim*ni, ti = Cre*ni + Cim*nr;
        float inv = 2.f/(are*are + aim*aim);
        s_cr[t] =  inv*(tr*are + ti*aim);
        s_ci[t] = -inv*(ti*are - tr*aim);
    }
    __syncthreads();
    const float Dh = Dp[h];
    __nv_bfloat16* GAh = g_GAh + (size_t)h*128*256;
    __nv_bfloat16* GAl = g_GAl + (size_t)h*128*256;
    __nv_bfloat16* GWh = g_GWh + (size_t)h*128*128;
    __nv_bfloat16* GWl = g_GWl + (size_t)h*128*128;

    for (int cd = 0; cd < 4; cd++) {
        if (t < 64) {
            float Lr = s_lr[t], Li = s_li[t];
            #pragma unroll
            for (int dd = 0; dd < 32; dd++) {
                s_pr[t][dd] = pr; s_pi[t][dd] = pi;
                float npr = pr*Lr - pi*Li;
                float npi = pr*Li + pi*Lr;
                pr = npr; pi = npi;
            }
        }
        __syncthreads();
        {
            int dd = t >> 2, q = t & 3;
            float part = 0.f;
            for (int n = q*16; n < q*16 + 16; n++)
                part += s_cr[n]*s_pr[n][dd] + s_ci[n]*s_pi[n][dd];
            part += __shfl_xor_sync(0xffffffffu, part, 1);
            part += __shfl_xor_sync(0xffffffffu, part, 2);
            int d = cd*32 + dd;
            if (q == 0) s_k[d] = part + (d == 0 ? Dh : 0.f);
        }
        for (int dd = 0; dd < 32; dd++) {
            int d = cd*32 + dd, r = d - 1;
            if (r >= 0) {
                float v;
                if (t < 64)
                    v = s_cr[t]*s_pr[t][dd] + s_ci[t]*s_pi[t][dd];
                else {
                    int j = t - 64;
                    v = s_ci[j]*s_pr[j][dd] - s_cr[j]*s_pi[j][dd];
                }
                __nv_bfloat16 hb, lb; bsplit(v, hb, lb);
                GAh[r*256 + 128 + t] = hb;
                GAl[r*256 + 128 + t] = lb;
            }
        }
        for (int p = 0; p < 32; p++) {
            int row = p*4 + (t >> 5);
            int sc = t & 31;
            int s = 96 - cd*32 + sc;
            int dd = 31 - sc;
            float v = (row < 64) ? s_pr[row][dd] : s_pi[row-64][dd];
            __nv_bfloat16 hb, lb; bsplit(v, hb, lb);
            GWh[row*128 + s] = hb;
            GWl[row*128 + s] = lb;
        }
        __syncthreads();
    }
    if (t < 64) { s_pr[t][0] = pr; s_pi[t][0] = pi; }
    __syncthreads();
    {
        float v;
        if (t < 64)
            v = s_cr[t]*s_pr[t][0] + s_ci[t]*s_pi[t][0];
        else {
            int j = t - 64;
            v = s_ci[j]*s_pr[j][0] - s_cr[j]*s_pi[j][0];
        }
        __nv_bfloat16 hb, lb; bsplit(v, hb, lb);
        GAh[127*256 + 128 + t] = hb;
        GAl[127*256 + 128 + t] = lb;
    }
    for (int r = 0; r < 128; r++) {
        float v = (t <= r) ? s_k[r - t] : 0.f;
        __nv_bfloat16 hb, lb; bsplit(v, hb, lb);
        GAh[r*256 + t] = hb;
        GAl[r*256 + t] = lb;
    }
}

// ---------------------------------------------------------------------------
// scanfix: compose Zend0 across chunks; write z0 (bf16 hi/lo) into X rows 128+
// ---------------------------------------------------------------------------
__global__ void __launch_bounds__(256) scanfix_kernel(
    const float* __restrict__ log_dt,
    const float* __restrict__ logA_re,
    const float* __restrict__ A_im)
{
    int gid = blockIdx.x*256 + threadIdx.x;
    int n = gid & 63, h = (gid >> 6) & 255, b = gid >> 14;

    float Lr, Li, are, aim;
    s4_lambda(log_dt, logA_re, A_im, h, n, Lr, Li, are, aim);
    #pragma unroll
    for (int s = 0; s < 7; s++) {
        float nr = Lr*Lr - Li*Li, ni = 2.f*Lr*Li;
        Lr = nr; Li = ni;
    }

    const float* zcre = g_zc + (size_t)h*128*MM + n*MM;
    const float* zcim = zcre + 64*MM;
    __nv_bfloat16* Xh = g_Xh + (size_t)h*MM*256;
    __nv_bfloat16* Xl = g_Xl + (size_t)h*MM*256;

    float cr = 0.f, ci = 0.f;
    #pragma unroll
    for (int c = 0; c < NC; c++) {
        int m = b*16 + c;
        __nv_bfloat16 hb, lb;
        bsplit(cr, hb, lb);
        Xh[(size_t)m*256 + 128 + n] = hb; Xl[(size_t)m*256 + 128 + n] = lb;
        bsplit(ci, hb, lb);
        Xh[(size_t)m*256 + 192 + n] = hb; Xl[(size_t)m*256 + 192 + n] = lb;
        float zr = zcre[m], zi = zcim[m];
        float nr = Lr*cr - Li*ci + zr;
        float ni = Lr*ci + Li*cr + zi;
        cr = nr; ci = ni;
    }
}

// ---------------------------------------------------------------------------
// GEMM building blocks
// ---------------------------------------------------------------------------
__device__ __forceinline__ void cp16(u32 dst, const void* src) {
    asm volatile("cp.async.cg.shared.global [%0], [%1], 16;" :: "r"(dst), "l"(src));
}
__device__ __forceinline__ void ldsm4(u32& r0, u32& r1, u32& r2, u32& r3, u32 addr) {
    asm volatile("ldmatrix.sync.aligned.m8n8.x4.shared.b16 {%0,%1,%2,%3},[%4];"
                 : "=r"(r0), "=r"(r1), "=r"(r2), "=r"(r3) : "r"(addr));
}
__device__ __forceinline__ void mma_bf16(float* d, const u32* a, const u32* b) {
    asm volatile(
        "mma.sync.aligned.m16n8k16.row.col.f32.bf16.bf16.f32 "
        "{%0,%1,%2,%3},{%4,%5,%6,%7},{%8,%9},{%0,%1,%2,%3};"
        : "+f"(d[0]), "+f"(d[1]), "+f"(d[2]), "+f"(d[3])
        : "r"(a[0]), "r"(a[1]), "r"(a[2]), "r"(a[3]), "r"(b[0]), "r"(b[1]));
}

// Stage layout: Ah 0 | Al 8K | Bh 16K | Bl 20K ; stage stride 24K; 2 stages = 48K
#define STG2 24576

// ---------------------------------------------------------------------------
// gemm_s4: per-channel bf16x3 (pass1: Zend0 = G_W*U, K=128; pass2: Y = G_A*X, K=256)
//   Combined-region loading: hi+lo of A and B staged once, 3 mma combos from regs.
// ---------------------------------------------------------------------------
__global__ void __launch_bounds__(256) gemm_s4_kernel(int pass)
{
    __shared__ __align__(128) char smem_buf[2*STG2];
    const int h  = blockIdx.y;
    const int mt = blockIdx.x;
    const int tid = threadIdx.x, lane = tid & 31, w = tid >> 5;
    const int wm = w & 3, wn = w >> 2;

    const int NK = (pass == 1) ? 128 : 256;
    const __nv_bfloat16* Ahp = (pass == 1) ? g_GWh + (size_t)h*128*128
                                           : g_GAh + (size_t)h*128*256;
    const __nv_bfloat16* Alp = (pass == 1) ? g_GWl + (size_t)h*128*128
                                           : g_GAl + (size_t)h*128*256;
    const __nv_bfloat16* Bhp = g_Xh + (size_t)h*MM*256;
    const __nv_bfloat16* Blp = g_Xl + (size_t)h*MM*256;
    float* outp = ((pass == 1) ? g_zc : g_y) + (size_t)h*128*MM;

    const int nch = NK/32;
    const u32 smem_base = (u32)__cvta_generic_to_shared(smem_buf);

    float acc[2][4][4];
    #pragma unroll
    for (int mi = 0; mi < 2; mi++)
        #pragma unroll
        for (int ni = 0; ni < 4; ni++)
            #pragma unroll
            for (int r = 0; r < 4; r++) acc[mi][ni][r] = 0.f;

    auto load_chunk = [&](int kc, int stage) {
        int k0 = kc*32;
        u32 base = smem_base + stage*STG2;
        #pragma unroll
        for (int i = 0; i < 2; i++) {
            int gid = i*256 + tid;
            int row = gid >> 2, g = gid & 3;
            int pg = g ^ ((row >> 1) & 3);
            cp16(base + row*64 + pg*16,        Ahp + (size_t)row*NK + k0 + g*8);
            cp16(base + 8192 + row*64 + pg*16, Alp + (size_t)row*NK + k0 + g*8);
        }
        {
            int row = tid >> 2, g = tid & 3;
            int pg = g ^ ((row >> 1) & 3);
            cp16(base + 16384 + row*64 + pg*16, Bhp + (size_t)(mt*64 + row)*256 + k0 + g*8);
            cp16(base + 20480 + row*64 + pg*16, Blp + (size_t)(mt*64 + row)*256 + k0 + g*8);
        }
    };

    load_chunk(0, 0);
    asm volatile("cp.async.commit_group;");

    for (int kc = 0; kc < nch; kc++) {
        if (kc + 1 < nch) load_chunk(kc + 1, (kc + 1) & 1);
        asm volatile("cp.async.commit_group;");
        asm volatile("cp.async.wait_group 1;");
        __syncthreads();

        const u32 ab  = smem_base + (kc & 1)*STG2;
        const u32 alb = ab + 8192, bhb = ab + 16384, blb = ab + 20480;

        #pragma unroll
        for (int ks = 0; ks < 2; ks++) {
            const int grp = lane >> 3, rh = lane & 7;
            u32 ah[2][4], al[2][4];
            #pragma unroll
            for (int mi = 0; mi < 2; mi++) {
                int row = wm*32 + mi*16 + rh + (grp & 1)*8;
                int kg  = 2*ks + (grp >> 1);
                u32 off = row*64 + ((kg ^ ((row >> 1) & 3))*16);
                ldsm4(ah[mi][0], ah[mi][1], ah[mi][2], ah[mi][3], ab + off);
                ldsm4(al[mi][0], al[mi][1], al[mi][2], al[mi][3], alb + off);
            }
            u32 bh[4][2], bl[4][2];
            #pragma unroll
            for (int nf = 0; nf < 2; nf++) {
                int row = wn*32 + nf*16 + rh + (grp >> 1)*8;
                int kg  = 2*ks + (grp & 1);
                u32 off = row*64 + ((kg ^ ((row >> 1) & 3))*16);
                u32 r0, r1, r2, r3;
                ldsm4(r0, r1, r2, r3, bhb + off);
                bh[nf*2][0] = r0; bh[nf*2][1] = r1;
                bh[nf*2+1][0] = r2; bh[nf*2+1][1] = r3;
                ldsm4(r0, r1, r2, r3, blb + off);
                bl[nf*2][0] = r0; bl[nf*2][1] = r1;
                bl[nf*2+1][0] = r2; bl[nf*2+1][1] = r3;
            }
            #pragma unroll
            for (int mi = 0; mi < 2; mi++)
                #pragma unroll
                for (int ni = 0; ni < 4; ni++) {
                    mma_bf16(acc[mi][ni], ah[mi], bh[ni]);
                    mma_bf16(acc[mi][ni], al[mi], bh[ni]);
                    mma_bf16(acc[mi][ni], ah[mi], bl[ni]);
                }
        }
        __syncthreads();
    }

    const int lq = lane >> 2, lc = lane & 3;
    #pragma unroll
    for (int mi = 0; mi < 2; mi++) {
        #pragma unroll
        for (int ni = 0; ni < 4; ni++) {
            int row = wm*32 + mi*16 + lq;
            int col = mt*64 + wn*32 + ni*8 + lc*2;
            float2 v0; v0.x = acc[mi][ni][0]; v0.y = acc[mi][ni][1];
            float2 v1; v1.x = acc[mi][ni][2]; v1.y = acc[mi][ni][3];
            *(float2*)(outp + (size_t)row*MM + col) = v0;
            *(float2*)(outp + (size_t)(row+8)*MM + col) = v1;
        }
    }
}

// ---------------------------------------------------------------------------
// backT: g_y (h,t,m) fp32 -> gelu -> g_gh/g_gl (row,h) bf16 hi/lo
// ---------------------------------------------------------------------------
__global__ void __launch_bounds__(256) backT_kernel()
{
    const int m0 = blockIdx.x*32, t0 = blockIdx.y*8, h0 = blockIdx.z*32;
    __shared__ float sB[256][33];
    const int tid = threadIdx.x, w = tid >> 5, lane = tid & 31;

    for (int i = 0; i < 32; i++) {
        int seg = w*32 + i;
        int hh = seg >> 3, tt = seg & 7;
        float v = g_y[(size_t)(h0+hh)*TT*MM + (size_t)(t0+tt)*MM + m0 + lane];
        sB[tt*32 + lane][hh] = v;
    }
    __syncthreads();
    for (int i = 0; i < 32; i++) {
        int pair = w*32 + i;
        int mm = pair >> 3, tt = pair & 7;
        int m = m0 + mm;
        int b = m >> 4, cc = m & 15;
        size_t row = (size_t)b*LL + cc*TT + t0 + tt;
        float yv = sB[tt*32 + mm][lane];
        float gv = 0.5f*yv*(1.0f + erff(yv*0.70710678118654752f));
        __nv_bfloat16 hb, lb; bsplit(gv, hb, lb);
        g_gh[row*HH + h0 + lane] = hb;
        g_gl[row*HH + h0 + lane] = lb;
    }
}

// ---------------------------------------------------------------------------
// GLU GEMM: bf16x3 with combined-region loading, fused GLU+bias+residual.
// ---------------------------------------------------------------------------
__global__ void __launch_bounds__(256) gemm_glu_kernel(int l, const float* __restrict__ bias)
{
    __shared__ __align__(128) char smem_buf[2*STG2];

    const int m0  = blockIdx.y * 128;
    const int nb  = blockIdx.x;
    const int tid = threadIdx.x;
    const int lane = tid & 31, w = tid >> 5;
    const int wm = w & 3;
    const int wn = w >> 2;

    const __nv_bfloat16* Whp = g_wh + (size_t)l*GN*GK;
    const __nv_bfloat16* Wlp = g_wl + (size_t)l*GN*GK;

    const u32 smem_base = (u32)__cvta_generic_to_shared(smem_buf);

    float acc[2][4][4];
    #pragma unroll
    for (int mi = 0; mi < 2; mi++)
        #pragma unroll
        for (int ni = 0; ni < 4; ni++)
            #pragma unroll
            for (int r = 0; r < 4; r++) acc[mi][ni][r] = 0.f;

    auto load_chunk = [&](int kc, int stage) {
        int k0 = kc*32;
        u32 base = smem_base + stage*STG2;
        #pragma unroll
        for (int i = 0; i < 2; i++) {
            int gid = i*256 + tid;
            int row = gid >> 2, g = gid & 3;
            int pg = g ^ ((row >> 1) & 3);
            cp16(base + row*64 + pg*16,        g_gh + (size_t)(m0 + row)*GK + k0 + g*8);
            cp16(base + 8192 + row*64 + pg*16, g_gl + (size_t)(m0 + row)*GK + k0 + g*8);
        }
        {
            int row = tid >> 2, g = tid & 3;
            int pg = g ^ ((row >> 1) & 3);
            int wr = nb*32 + (row >> 1) + (row & 1)*256;
            cp16(base + 16384 + row*64 + pg*16, Whp + (size_t)wr*GK + k0 + g*8);
            cp16(base + 20480 + row*64 + pg*16, Wlp + (size_t)wr*GK + k0 + g*8);
        }
    };

    load_chunk(0, 0);
    asm volatile("cp.async.commit_group;");

    #pragma unroll 1
    for (int kc = 0; kc < 8; kc++) {
        if (kc + 1 < 8) load_chunk(kc + 1, (kc + 1) & 1);
        asm volatile("cp.async.commit_group;");
        asm volatile("cp.async.wait_group 1;");
        __syncthreads();

        const u32 ab  = smem_base + (kc & 1)*STG2;
        const u32 alb = ab + 8192, bhb = ab + 16384, blb = ab + 20480;

        #pragma unroll
        for (int ks = 0; ks < 2; ks++) {
            const int grp = lane >> 3, rh = lane & 7;
            u32 ah[2][4], al[2][4];
            #pragma unroll
            for (int mi = 0; mi < 2; mi++) {
                int row = wm*32 + mi*16 + rh + (grp & 1)*8;
                int kg  = 2*ks + (grp >> 1);
                u32 off = row*64 + ((kg ^ ((row >> 1) & 3))*16);
                ldsm4(ah[mi][0], ah[mi][1], ah[mi][2], ah[mi][3], ab + off);
                ldsm4(al[mi][0], al[mi][1], al[mi][2], al[mi][3], alb + off);
            }
            u32 bh[4][2], bl[4][2];
            #pragma unroll
            for (int nf = 0; nf < 2; nf++) {
                int row = wn*32 + nf*16 + rh + (grp >> 1)*8;
                int kg  = 2*ks + (grp & 1);
                u32 off = row*64 + ((kg ^ ((row >> 1) & 3))*16);
                u32 r0, r1, r2, r3;
                ldsm4(r0, r1, r2, r3, bhb + off);
                bh[nf*2][0] = r0; bh[nf*2][1] = r1;
                bh[nf*2+1][0] = r2; bh[nf*2+1][1] = r3;
                ldsm4(r0, r1, r2, r3, blb + off);
                bl[nf*2][0] = r0; bl[nf*2][1] = r1;
                bl[nf*2+1][0] = r2; bl[nf*2+1][1] = r3;
            }
            #pragma unroll
            for (int mi = 0; mi < 2; mi++)
                #pragma unroll
                for (int ni = 0; ni < 4; ni++) {
                    mma_bf16(acc[mi][ni], ah[mi], bh[ni]);
                    mma_bf16(acc[mi][ni], al[mi], bh[ni]);
                    mma_bf16(acc[mi][ni], ah[mi], bl[ni]);
                }
        }
        __syncthreads();
    }

    const int lc = lane & 3, lq = lane >> 2;
    #pragma unroll
    for (int ni = 0; ni < 4; ni++) {
        const int oc = nb*32 + wn*16 + ni*4 + lc;
        const float bL = bias[oc];
        const float bR = bias[oc + 256];
        #pragma unroll
        for (int mi = 0; mi < 2; mi++) {
            int mg = m0 + wm*32 + mi*16 + lq;
            {
                float zl = acc[mi][ni][0] + bL;
                float zr_ = acc[mi][ni][1] + bR;
                float sv = zl * (1.0f/(1.0f + expf(-zr_))) + g_x[(size_t)mg*HH + oc];
                g_s[(size_t)mg*HH + oc] = sv;
            }
            {
                int mg2 = mg + 8;
                float zl = acc[mi][ni][2] + bL;
                float zr_ = acc[mi][ni][3] + bR;
                float sv = zl * (1.0f/(1.0f + expf(-zr_))) + g_x[(size_t)mg2*HH + oc];
                g_s[(size_t)mg2*HH + oc] = sv;
            }
        }
    }
}

// ---------------------------------------------------------------------------
// LayerNorm warp-per-row + fused heads on last layer
// ---------------------------------------------------------------------------
__device__ __forceinline__ float softplus_f(float x) {
    return fmaxf(x, 0.f) + log1pf(expf(-fabsf(x)));
}

__global__ void __launch_bounds__(256) ln_kernel(
    const float* __restrict__ lng, const float* __restrict__ lnb,
    const float* __restrict__ mu_w, const float* __restrict__ mu_b,
    const float* __restrict__ al_w, const float* __restrict__ al_b,
    float* __restrict__ out, int half, int do_head)
{
    const int w = threadIdx.x >> 5, lane = threadIdx.x & 31;
    const int row = blockIdx.x*8 + w;
    const float4* sp = (const float4*)(g_s + (size_t)row*HH);
    float4 v0 = sp[lane];
    float4 v1 = sp[lane + 32];

    float s1 = v0.x+v0.y+v0.z+v0.w + v1.x+v1.y+v1.z+v1.w;
    float s2 = v0.x*v0.x+v0.y*v0.y+v0.z*v0.z+v0.w*v0.w
             + v1.x*v1.x+v1.y*v1.y+v1.z*v1.z+v1.w*v1.w;
    #pragma unroll
    for (int o = 16; o > 0; o >>= 1) {
        s1 += __shfl_xor_sync(0xffffffffu, s1, o);
        s2 += __shfl_xor_sync(0xffffffffu, s2, o);
    }
    float mean = s1 * (1.0f/HH);
    float var  = s2 * (1.0f/HH) - mean*mean;
    float inv  = rsqrtf(var + 1e-5f);

    const float4* gp = (const float4*)lng;
    const float4* bp = (const float4*)lnb;
    float4 g0 = gp[lane], g1 = gp[lane+32];
    float4 b0 = bp[lane], b1 = bp[lane+32];
    float4 y0, y1;
    y0.x = (v0.x-mean)*inv*g0.x + b0.x;  y0.y = (v0.y-mean)*inv*g0.y + b0.y;
    y0.z = (v0.z-mean)*inv*g0.z + b0.z;  y0.w = (v0.w-mean)*inv*g0.w + b0.w;
    y1.x = (v1.x-mean)*inv*g1.x + b1.x;  y1.y = (v1.y-mean)*inv*g1.y + b1.y;
    y1.z = (v1.z-mean)*inv*g1.z + b1.z;  y1.w = (v1.w-mean)*inv*g1.w + b1.w;

    float4* xp = (float4*)(g_x + (size_t)row*HH);
    xp[lane] = y0;
    xp[lane + 32] = y1;

    if (do_head) {
        const float4* mp = (const float4*)mu_w;
        const float4* ap = (const float4*)al_w;
        float4 m0 = mp[lane], m1 = mp[lane+32];
        float4 a0 = ap[lane], a1 = ap[lane+32];
        float sm = y0.x*m0.x + y0.y*m0.y + y0.z*m0.z + y0.w*m0.w
                 + y1.x*m1.x + y1.y*m1.y + y1.z*m1.z + y1.w*m1.w;
        float sa = y0.x*a0.x + y0.y*a0.y + y0.z*a0.z + y0.w*a0.w
                 + y1.x*a1.x + y1.y*a1.y + y1.z*a1.z + y1.w*a1.w;
        #pragma unroll
        for (int o = 16; o > 0; o >>= 1) {
            sm += __shfl_xor_sync(0xffffffffu, sm, o);
            sa += __shfl_xor_sync(0xffffffffu, sa, o);
        }
        if (lane == 0) {
            out[row]        = softplus_f(sm + mu_b[0]);
            out[half + row] = softplus_f(sa + al_b[0]);
        }
    }
}

// ---------------------------------------------------------------------------
extern "C" void kernel_launch(void* const* d_in, const int* in_sizes, int n_in,
                              void* d_out, int out_size)
{
    const float* x      = (const float*)d_in[0];
    const float* enc_w  = (const float*)d_in[1];
    const float* enc_b  = (const float*)d_in[2];
    const float* log_dt = (const float*)d_in[3];
    const float* logA   = (const float*)d_in[4];
    const float* A_im   = (const float*)d_in[5];
    const float* C_re   = (const float*)d_in[6];
    const float* C_im   = (const float*)d_in[7];
    const float* Dp     = (const float*)d_in[8];
    const float* out_w  = (const float*)d_in[9];
    const float* out_b  = (const float*)d_in[10];
    const float* ln_g   = (const float*)d_in[11];
    const float* ln_b   = (const float*)d_in[12];
    const float* mu_w   = (const float*)d_in[13];
    const float* mu_b   = (const float*)d_in[14];
    const float* al_w   = (const float*)d_in[15];
    const float* al_b   = (const float*)d_in[16];
    float* out = (float*)d_out;

    enc_kernel<<<GM, HH>>>(x, enc_w, enc_b);
    wconv_kernel<<<(NLAYERS*GN*GK)/256, 256>>>(out_w);

    for (int l = 0; l < NLAYERS; l++) {
        const float* ldt = log_dt + l*HH;
        const float* lA  = logA   + (size_t)l*HH*NN;
        const float* Ai  = A_im   + (size_t)l*HH*NN;

        fwdT_kernel<<<dim3(MM, 8), 256>>>();
        genG_kernel<<<HH, 128>>>(ldt, lA, Ai,
                                 C_re + (size_t)l*HH*NN,
                                 C_im + (size_t)l*HH*NN,
                                 Dp + l*HH);
        gemm_s4_kernel<<<dim3(4, HH), 256>>>(1);
        scanfix_kernel<<<(BB*HH*NN)/256, 256>>>(ldt, lA, Ai);
        gemm_s4_kernel<<<dim3(4, HH), 256>>>(2);
        backT_kernel<<<dim3(MM/32, TT/8, HH/32), 256>>>();
        gemm_glu_kernel<<<dim3(8, GM/128), 256>>>(l, out_b + (size_t)l*GN);
        ln_kernel<<<GM/8, 256>>>(ln_g + l*HH, ln_b + l*HH,
                                 mu_w, mu_b, al_w, al_b,
                                 out, out_size/2, (l == NLAYERS-1) ? 1 : 0);
    }
}

// round 8
// speedup vs baseline: 2.4608x; 1.0186x over previous
#include <cuda_runtime.h>
#include <cuda_bf16.h>
#include <math.h>

// Problem constants
#define BB 16
#define LL 2048
#define DIN 8
#define HH 256
#define NN 64
#define NLAYERS 4
#define GM (BB*LL)      // 32768 rows
#define GK HH           // 256
#define GN (2*HH)       // 512
#define NC 16           // time chunks
#define TT (LL/NC)      // 128
#define MM (BB*NC)      // 256 chunk-columns

typedef unsigned long long ull;
typedef unsigned int u32;

// Scratch (device globals)
__device__ float g_x[(size_t)GM*HH];                       // activations (row,h)
__device__ float g_s[(size_t)GM*HH];                       // pre-LN (row,h)
__device__ __nv_bfloat16 g_gh[(size_t)GM*HH];              // gelu out hi (row,h)
__device__ __nv_bfloat16 g_gl[(size_t)GM*HH];              // gelu out lo
__device__ __nv_bfloat16 g_wh[(size_t)NLAYERS*GN*GK];      // GLU W hi
__device__ __nv_bfloat16 g_wl[(size_t)NLAYERS*GN*GK];      // GLU W lo
__device__ __nv_bfloat16 g_Xh[(size_t)HH*MM*256];          // X=[u;z0] hi (h,m,k)
__device__ __nv_bfloat16 g_Xl[(size_t)HH*MM*256];          // X lo
__device__ __nv_bfloat16 g_GAh[(size_t)NLAYERS*HH*128*256];// [K|V] hi (l,h,r,k)
__device__ __nv_bfloat16 g_GAl[(size_t)NLAYERS*HH*128*256];
__device__ __nv_bfloat16 g_GWh[(size_t)NLAYERS*HH*128*128];// W hi (l,h,i,s)
__device__ __nv_bfloat16 g_GWl[(size_t)NLAYERS*HH*128*128];
__device__ float g_zc[(size_t)HH*128*MM];                  // Zend0 (h,i,m)
__device__ float g_y[(size_t)HH*TT*MM];                    // conv out (h,t,m)

__device__ __forceinline__ void bsplit(float v, __nv_bfloat16& h, __nv_bfloat16& l) {
    h = __float2bfloat16_rn(v);
    l = __float2bfloat16_rn(v - __bfloat162float(h));
}

// ---------------------------------------------------------------------------
// Encoder (row,h)
// ---------------------------------------------------------------------------
__global__ void enc_kernel(const float* __restrict__ x,
                           const float* __restrict__ w,
                           const float* __restrict__ b)
{
    int row = blockIdx.x;
    int h = threadIdx.x;
    __shared__ float xr[DIN];
    if (h < DIN) xr[h] = x[row*DIN + h];
    __syncthreads();
    float s = b[h];
    #pragma unroll
    for (int k = 0; k < DIN; k++)
        s = fmaf(xr[k], w[h*DIN + k], s);
    g_x[(size_t)row*HH + h] = s;
}

// ---------------------------------------------------------------------------
// One-shot GLU W -> bf16 hi/lo split
// ---------------------------------------------------------------------------
__global__ void wconv_kernel(const float* __restrict__ W)
{
    size_t i = (size_t)blockIdx.x*256 + threadIdx.x;
    float w = W[i];
    bsplit(w, g_wh[i], g_wl[i]);
}

// ---------------------------------------------------------------------------
__device__ __forceinline__ void s4_lambda(
    const float* log_dt, const float* logA_re, const float* A_im,
    int h, int n, float& Lr, float& Li, float& are, float& aim)
{
    float dt = expf(log_dt[h]);
    are = -expf(logA_re[h*NN + n]);
    aim = A_im[h*NN + n];
    float er = expf(dt*are);
    float dim = dt*aim;
    Lr = er*cosf(dim);
    Li = er*sinf(dim);
}

// ---------------------------------------------------------------------------
// fwdT: g_x (row,h) fp32 -> X (h, m, t) bf16 hi/lo (k-cols 0..127)
// ---------------------------------------------------------------------------
__global__ void __launch_bounds__(256) fwdT_kernel()
{
    const int m = blockIdx.x, h0 = blockIdx.y*32;
    const int b = m >> 4, c = m & 15;
    const size_t rbase = ((size_t)b*LL + c*TT)*HH;
    __shared__ float sT[128][33];
    const int tid = threadIdx.x;
    const int hl = (tid & 7)*4, tr0 = tid >> 3;
    #pragma unroll
    for (int p = 0; p < 4; p++) {
        int tt = p*32 + tr0;
        float4 v = *(const float4*)(g_x + rbase + (size_t)tt*HH + h0 + hl);
        sT[tt][hl] = v.x; sT[tt][hl+1] = v.y; sT[tt][hl+2] = v.z; sT[tt][hl+3] = v.w;
    }
    __syncthreads();
    const int w = tid >> 5, lane = tid & 31;
    union P4 { __nv_bfloat16 b[4]; ull u; };
    #pragma unroll
    for (int p = 0; p < 4; p++) {
        int hh = p*8 + w;
        int t0 = lane*4;
        P4 ph, pl;
        #pragma unroll
        for (int i = 0; i < 4; i++) bsplit(sT[t0+i][hh], ph.b[i], pl.b[i]);
        size_t dst = (size_t)(h0+hh)*((size_t)MM*256) + (size_t)m*256 + t0;
        *(ull*)(g_Xh + dst) = ph.u;
        *(ull*)(g_Xl + dst) = pl.u;
    }
}

// ---------------------------------------------------------------------------
// genG_all: per-(layer,channel) G_A=[K|V] (128x256), G_W (128x128), bf16 hi/lo.
//   grid (HH, NLAYERS), block 128. Hoisted out of the layer loop.
// ---------------------------------------------------------------------------
__global__ void __launch_bounds__(128) genG_all_kernel(
    const float* __restrict__ log_dt_a,
    const float* __restrict__ logA_a,
    const float* __restrict__ A_im_a,
    const float* __restrict__ C_re_a,
    const float* __restrict__ C_im_a,
    const float* __restrict__ Dp_a)
{
    const int h = blockIdx.x;
    const int l = blockIdx.y;
    const int t = threadIdx.x;
    const float* log_dt = log_dt_a + l*HH;
    const float* logA_re = logA_a + (size_t)l*HH*NN;
    const float* A_im = A_im_a + (size_t)l*HH*NN;
    const float* C_re = C_re_a + (size_t)l*HH*NN;
    const float* C_im = C_im_a + (size_t)l*HH*NN;

    __shared__ float s_cr[64], s_ci[64], s_lr[64], s_li[64];
    __shared__ float s_pr[64][33], s_pi[64][33];
    __shared__ float s_k[128];

    float pr = 1.f, pi = 0.f;
    if (t < 64) {
        float are, aim, Lr, Li;
        s4_lambda(log_dt, logA_re, A_im, h, t, Lr, Li, are, aim);
        s_lr[t] = Lr; s_li[t] = Li;
        float Cre = C_re[h*NN + t], Cim = C_im[h*NN + t];
        float nr = Lr - 1.f, ni = Li;
        float tr = Cre*nr - Cim*ni, ti = Cre*ni + Cim*nr;
        float inv = 2.f/(are*are + aim*aim);
        s_cr[t] =  inv*(tr*are + ti*aim);
        s_ci[t] = -inv*(ti*are - tr*aim);
    }
    __syncthreads();
    const float Dh = Dp_a[l*HH + h];
    __nv_bfloat16* GAh = g_GAh + ((size_t)l*HH + h)*128*256;
    __nv_bfloat16* GAl = g_GAl + ((size_t)l*HH + h)*128*256;
    __nv_bfloat16* GWh = g_GWh + ((size_t)l*HH + h)*128*128;
    __nv_bfloat16* GWl = g_GWl + ((size_t)l*HH + h)*128*128;

    for (int cd = 0; cd < 4; cd++) {
        if (t < 64) {
            float Lr = s_lr[t], Li = s_li[t];
            #pragma unroll
            for (int dd = 0; dd < 32; dd++) {
                s_pr[t][dd] = pr; s_pi[t][dd] = pi;
                float npr = pr*Lr - pi*Li;
                float npi = pr*Li + pi*Lr;
                pr = npr; pi = npi;
            }
        }
        __syncthreads();
        {
            int dd = t >> 2, q = t & 3;
            float part = 0.f;
            for (int n = q*16; n < q*16 + 16; n++)
                part += s_cr[n]*s_pr[n][dd] + s_ci[n]*s_pi[n][dd];
            part += __shfl_xor_sync(0xffffffffu, part, 1);
            part += __shfl_xor_sync(0xffffffffu, part, 2);
            int d = cd*32 + dd;
            if (q == 0) s_k[d] = part + (d == 0 ? Dh : 0.f);
        }
        for (int dd = 0; dd < 32; dd++) {
            int d = cd*32 + dd, r = d - 1;
            if (r >= 0) {
                float v;
                if (t < 64)
                    v = s_cr[t]*s_pr[t][dd] + s_ci[t]*s_pi[t][dd];
                else {
                    int j = t - 64;
                    v = s_ci[j]*s_pr[j][dd] - s_cr[j]*s_pi[j][dd];
                }
                __nv_bfloat16 hb, lb; bsplit(v, hb, lb);
                GAh[r*256 + 128 + t] = hb;
                GAl[r*256 + 128 + t] = lb;
            }
        }
        for (int p = 0; p < 32; p++) {
            int row = p*4 + (t >> 5);
            int sc = t & 31;
            int s = 96 - cd*32 + sc;
            int dd = 31 - sc;
            float v = (row < 64) ? s_pr[row][dd] : s_pi[row-64][dd];
            __nv_bfloat16 hb, lb; bsplit(v, hb, lb);
            GWh[row*128 + s] = hb;
            GWl[row*128 + s] = lb;
        }
        __syncthreads();
    }
    if (t < 64) { s_pr[t][0] = pr; s_pi[t][0] = pi; }
    __syncthreads();
    {
        float v;
        if (t < 64)
            v = s_cr[t]*s_pr[t][0] + s_ci[t]*s_pi[t][0];
        else {
            int j = t - 64;
            v = s_ci[j]*s_pr[j][0] - s_cr[j]*s_pi[j][0];
        }
        __nv_bfloat16 hb, lb; bsplit(v, hb, lb);
        GAh[127*256 + 128 + t] = hb;
        GAl[127*256 + 128 + t] = lb;
    }
    for (int r = 0; r < 128; r++) {
        float v = (t <= r) ? s_k[r - t] : 0.f;
        __nv_bfloat16 hb, lb; bsplit(v, hb, lb);
        GAh[r*256 + t] = hb;
        GAl[r*256 + t] = lb;
    }
}

// ---------------------------------------------------------------------------
// scanfix: compose Zend0 across chunks; write z0 (bf16 hi/lo) into X rows 128+
// ---------------------------------------------------------------------------
__global__ void __launch_bounds__(256) scanfix_kernel(
    const float* __restrict__ log_dt,
    const float* __restrict__ logA_re,
    const float* __restrict__ A_im)
{
    int gid = blockIdx.x*256 + threadIdx.x;
    int n = gid & 63, h = (gid >> 6) & 255, b = gid >> 14;

    float Lr, Li, are, aim;
    s4_lambda(log_dt, logA_re, A_im, h, n, Lr, Li, are, aim);
    #pragma unroll
    for (int s = 0; s < 7; s++) {
        float nr = Lr*Lr - Li*Li, ni = 2.f*Lr*Li;
        Lr = nr; Li = ni;
    }

    const float* zcre = g_zc + (size_t)h*128*MM + n*MM;
    const float* zcim = zcre + 64*MM;
    __nv_bfloat16* Xh = g_Xh + (size_t)h*MM*256;
    __nv_bfloat16* Xl = g_Xl + (size_t)h*MM*256;

    float cr = 0.f, ci = 0.f;
    #pragma unroll
    for (int c = 0; c < NC; c++) {
        int m = b*16 + c;
        __nv_bfloat16 hb, lb;
        bsplit(cr, hb, lb);
        Xh[(size_t)m*256 + 128 + n] = hb; Xl[(size_t)m*256 + 128 + n] = lb;
        bsplit(ci, hb, lb);
        Xh[(size_t)m*256 + 192 + n] = hb; Xl[(size_t)m*256 + 192 + n] = lb;
        float zr = zcre[m], zi = zcim[m];
        float nr = Lr*cr - Li*ci + zr;
        float ni = Lr*ci + Li*cr + zi;
        cr = nr; ci = ni;
    }
}

// ---------------------------------------------------------------------------
// GEMM building blocks (mma.sync path — sm_100 plain target)
// ---------------------------------------------------------------------------
__device__ __forceinline__ void cp16(u32 dst, const void* src) {
    asm volatile("cp.async.cg.shared.global [%0], [%1], 16;" :: "r"(dst), "l"(src));
}
__device__ __forceinline__ void ldsm4(u32& r0, u32& r1, u32& r2, u32& r3, u32 addr) {
    asm volatile("ldmatrix.sync.aligned.m8n8.x4.shared.b16 {%0,%1,%2,%3},[%4];"
                 : "=r"(r0), "=r"(r1), "=r"(r2), "=r"(r3) : "r"(addr));
}
__device__ __forceinline__ void mma_bf16(float* d, const u32* a, const u32* b) {
    asm volatile(
        "mma.sync.aligned.m16n8k16.row.col.f32.bf16.bf16.f32 "
        "{%0,%1,%2,%3},{%4,%5,%6,%7},{%8,%9},{%0,%1,%2,%3};"
        : "+f"(d[0]), "+f"(d[1]), "+f"(d[2]), "+f"(d[3])
        : "r"(a[0]), "r"(a[1]), "r"(a[2]), "r"(a[3]), "r"(b[0]), "r"(b[1]));
}

// Stage layout: Ah 0 | Al 8K | Bh 16K | Bl 20K ; stage stride 24K; 2 stages = 48K
#define STG2 24576

// ---------------------------------------------------------------------------
// gemm_s4: per-channel bf16x3 (pass1: Zend0 = G_W*U, K=128; pass2: Y = G_A*X, K=256)
// ---------------------------------------------------------------------------
__global__ void __launch_bounds__(256) gemm_s4_kernel(int pass, int l)
{
    __shared__ __align__(128) char smem_buf[2*STG2];
    const int h  = blockIdx.y;
    const int mt = blockIdx.x;
    const int tid = threadIdx.x, lane = tid & 31, w = tid >> 5;
    const int wm = w & 3, wn = w >> 2;

    const int NK = (pass == 1) ? 128 : 256;
    const __nv_bfloat16* Ahp = (pass == 1) ? g_GWh + ((size_t)l*HH + h)*128*128
                                           : g_GAh + ((size_t)l*HH + h)*128*256;
    const __nv_bfloat16* Alp = (pass == 1) ? g_GWl + ((size_t)l*HH + h)*128*128
                                           : g_GAl + ((size_t)l*HH + h)*128*256;
    const __nv_bfloat16* Bhp = g_Xh + (size_t)h*MM*256;
    const __nv_bfloat16* Blp = g_Xl + (size_t)h*MM*256;
    float* outp = ((pass == 1) ? g_zc : g_y) + (size_t)h*128*MM;

    const int nch = NK/32;
    const u32 smem_base = (u32)__cvta_generic_to_shared(smem_buf);

    float acc[2][4][4];
    #pragma unroll
    for (int mi = 0; mi < 2; mi++)
        #pragma unroll
        for (int ni = 0; ni < 4; ni++)
            #pragma unroll
            for (int r = 0; r < 4; r++) acc[mi][ni][r] = 0.f;

    auto load_chunk = [&](int kc, int stage) {
        int k0 = kc*32;
        u32 base = smem_base + stage*STG2;
        #pragma unroll
        for (int i = 0; i < 2; i++) {
            int gid = i*256 + tid;
            int row = gid >> 2, g = gid & 3;
            int pg = g ^ ((row >> 1) & 3);
            cp16(base + row*64 + pg*16,        Ahp + (size_t)row*NK + k0 + g*8);
            cp16(base + 8192 + row*64 + pg*16, Alp + (size_t)row*NK + k0 + g*8);
        }
        {
            int row = tid >> 2, g = tid & 3;
            int pg = g ^ ((row >> 1) & 3);
            cp16(base + 16384 + row*64 + pg*16, Bhp + (size_t)(mt*64 + row)*256 + k0 + g*8);
            cp16(base + 20480 + row*64 + pg*16, Blp + (size_t)(mt*64 + row)*256 + k0 + g*8);
        }
    };

    load_chunk(0, 0);
    asm volatile("cp.async.commit_group;");

    for (int kc = 0; kc < nch; kc++) {
        if (kc + 1 < nch) load_chunk(kc + 1, (kc + 1) & 1);
        asm volatile("cp.async.commit_group;");
        asm volatile("cp.async.wait_group 1;");
        __syncthreads();

        const u32 ab  = smem_base + (kc & 1)*STG2;
        const u32 alb = ab + 8192, bhb = ab + 16384, blb = ab + 20480;

        #pragma unroll
        for (int ks = 0; ks < 2; ks++) {
            const int grp = lane >> 3, rh = lane & 7;
            u32 ah[2][4], al[2][4];
            #pragma unroll
            for (int mi = 0; mi < 2; mi++) {
                int row = wm*32 + mi*16 + rh + (grp & 1)*8;
                int kg  = 2*ks + (grp >> 1);
                u32 off = row*64 + ((kg ^ ((row >> 1) & 3))*16);
                ldsm4(ah[mi][0], ah[mi][1], ah[mi][2], ah[mi][3], ab + off);
                ldsm4(al[mi][0], al[mi][1], al[mi][2], al[mi][3], alb + off);
            }
            u32 bh[4][2], bl[4][2];
            #pragma unroll
            for (int nf = 0; nf < 2; nf++) {
                int row = wn*32 + nf*16 + rh + (grp >> 1)*8;
                int kg  = 2*ks + (grp & 1);
                u32 off = row*64 + ((kg ^ ((row >> 1) & 3))*16);
                u32 r0, r1, r2, r3;
                ldsm4(r0, r1, r2, r3, bhb + off);
                bh[nf*2][0] = r0; bh[nf*2][1] = r1;
                bh[nf*2+1][0] = r2; bh[nf*2+1][1] = r3;
                ldsm4(r0, r1, r2, r3, blb + off);
                bl[nf*2][0] = r0; bl[nf*2][1] = r1;
                bl[nf*2+1][0] = r2; bl[nf*2+1][1] = r3;
            }
            #pragma unroll
            for (int mi = 0; mi < 2; mi++)
                #pragma unroll
                for (int ni = 0; ni < 4; ni++) {
                    mma_bf16(acc[mi][ni], ah[mi], bh[ni]);
                    mma_bf16(acc[mi][ni], al[mi], bh[ni]);
                    mma_bf16(acc[mi][ni], ah[mi], bl[ni]);
                }
        }
        __syncthreads();
    }

    const int lq = lane >> 2, lc = lane & 3;
    #pragma unroll
    for (int mi = 0; mi < 2; mi++) {
        #pragma unroll
        for (int ni = 0; ni < 4; ni++) {
            int row = wm*32 + mi*16 + lq;
            int col = mt*64 + wn*32 + ni*8 + lc*2;
            float2 v0; v0.x = acc[mi][ni][0]; v0.y = acc[mi][ni][1];
            float2 v1; v1.x = acc[mi][ni][2]; v1.y = acc[mi][ni][3];
            *(float2*)(outp + (size_t)row*MM + col) = v0;
            *(float2*)(outp + (size_t)(row+8)*MM + col) = v1;
        }
    }
}

// ---------------------------------------------------------------------------
// backT: g_y (h,t,m) fp32 -> gelu -> g_gh/g_gl (row,h) bf16 hi/lo
// ---------------------------------------------------------------------------
__global__ void __launch_bounds__(256) backT_kernel()
{
    const int m0 = blockIdx.x*32, t0 = blockIdx.y*8, h0 = blockIdx.z*32;
    __shared__ float sB[256][33];
    const int tid = threadIdx.x, w = tid >> 5, lane = tid & 31;

    for (int i = 0; i < 32; i++) {
        int seg = w*32 + i;
        int hh = seg >> 3, tt = seg & 7;
        float v = g_y[(size_t)(h0+hh)*TT*MM + (size_t)(t0+tt)*MM + m0 + lane];
        sB[tt*32 + lane][hh] = v;
    }
    __syncthreads();
    for (int i = 0; i < 32; i++) {
        int pair = w*32 + i;
        int mm = pair >> 3, tt = pair & 7;
        int m = m0 + mm;
        int b = m >> 4, cc = m & 15;
        size_t row = (size_t)b*LL + cc*TT + t0 + tt;
        float yv = sB[tt*32 + mm][lane];
        float gv = 0.5f*yv*(1.0f + erff(yv*0.70710678118654752f));
        __nv_bfloat16 hb, lb; bsplit(gv, hb, lb);
        g_gh[row*HH + h0 + lane] = hb;
        g_gl[row*HH + h0 + lane] = lb;
    }
}

// ---------------------------------------------------------------------------
// GLU GEMM: bf16x3 with combined-region loading, fused GLU+bias+residual.
// ---------------------------------------------------------------------------
__global__ void __launch_bounds__(256) gemm_glu_kernel(int l, const float* __restrict__ bias)
{
    __shared__ __align__(128) char smem_buf[2*STG2];

    const int m0  = blockIdx.y * 128;
    const int nb  = blockIdx.x;
    const int tid = threadIdx.x;
    const int lane = tid & 31, w = tid >> 5;
    const int wm = w & 3;
    const int wn = w >> 2;

    const __nv_bfloat16* Whp = g_wh + (size_t)l*GN*GK;
    const __nv_bfloat16* Wlp = g_wl + (size_t)l*GN*GK;

    const u32 smem_base = (u32)__cvta_generic_to_shared(smem_buf);

    float acc[2][4][4];
    #pragma unroll
    for (int mi = 0; mi < 2; mi++)
        #pragma unroll
        for (int ni = 0; ni < 4; ni++)
            #pragma unroll
            for (int r = 0; r < 4; r++) acc[mi][ni][r] = 0.f;

    auto load_chunk = [&](int kc, int stage) {
        int k0 = kc*32;
        u32 base = smem_base + stage*STG2;
        #pragma unroll
        for (int i = 0; i < 2; i++) {
            int gid = i*256 + tid;
            int row = gid >> 2, g = gid & 3;
            int pg = g ^ ((row >> 1) & 3);
            cp16(base + row*64 + pg*16,        g_gh + (size_t)(m0 + row)*GK + k0 + g*8);
            cp16(base + 8192 + row*64 + pg*16, g_gl + (size_t)(m0 + row)*GK + k0 + g*8);
        }
        {
            int row = tid >> 2, g = tid & 3;
            int pg = g ^ ((row >> 1) & 3);
            int wr = nb*32 + (row >> 1) + (row & 1)*256;
            cp16(base + 16384 + row*64 + pg*16, Whp + (size_t)wr*GK + k0 + g*8);
            cp16(base + 20480 + row*64 + pg*16, Wlp + (size_t)wr*GK + k0 + g*8);
        }
    };

    load_chunk(0, 0);
    asm volatile("cp.async.commit_group;");

    #pragma unroll 1
    for (int kc = 0; kc < 8; kc++) {
        if (kc + 1 < 8) load_chunk(kc + 1, (kc + 1) & 1);
        asm volatile("cp.async.commit_group;");
        asm volatile("cp.async.wait_group 1;");
        __syncthreads();

        const u32 ab  = smem_base + (kc & 1)*STG2;
        const u32 alb = ab + 8192, bhb = ab + 16384, blb = ab + 20480;

        #pragma unroll
        for (int ks = 0; ks < 2; ks++) {
            const int grp = lane >> 3, rh = lane & 7;
            u32 ah[2][4], al[2][4];
            #pragma unroll
            for (int mi = 0; mi < 2; mi++) {
                int row = wm*32 + mi*16 + rh + (grp & 1)*8;
                int kg  = 2*ks + (grp >> 1);
                u32 off = row*64 + ((kg ^ ((row >> 1) & 3))*16);
                ldsm4(ah[mi][0], ah[mi][1], ah[mi][2], ah[mi][3], ab + off);
                ldsm4(al[mi][0], al[mi][1], al[mi][2], al[mi][3], alb + off);
            }
            u32 bh[4][2], bl[4][2];
            #pragma unroll
            for (int nf = 0; nf < 2; nf++) {
                int row = wn*32 + nf*16 + rh + (grp >> 1)*8;
                int kg  = 2*ks + (grp & 1);
                u32 off = row*64 + ((kg ^ ((row >> 1) & 3))*16);
                u32 r0, r1, r2, r3;
                ldsm4(r0, r1, r2, r3, bhb + off);
                bh[nf*2][0] = r0; bh[nf*2][1] = r1;
                bh[nf*2+1][0] = r2; bh[nf*2+1][1] = r3;
                ldsm4(r0, r1, r2, r3, blb + off);
                bl[nf*2][0] = r0; bl[nf*2][1] = r1;
                bl[nf*2+1][0] = r2; bl[nf*2+1][1] = r3;
            }
            #pragma unroll
            for (int mi = 0; mi < 2; mi++)
                #pragma unroll
                for (int ni = 0; ni < 4; ni++) {
                    mma_bf16(acc[mi][ni], ah[mi], bh[ni]);
                    mma_bf16(acc[mi][ni], al[mi], bh[ni]);
                    mma_bf16(acc[mi][ni], ah[mi], bl[ni]);
                }
        }
        __syncthreads();
    }

    const int lc = lane & 3, lq = lane >> 2;
    #pragma unroll
    for (int ni = 0; ni < 4; ni++) {
        const int oc = nb*32 + wn*16 + ni*4 + lc;
        const float bL = bias[oc];
        const float bR = bias[oc + 256];
        #pragma unroll
        for (int mi = 0; mi < 2; mi++) {
            int mg = m0 + wm*32 + mi*16 + lq;
            {
                float zl = acc[mi][ni][0] + bL;
                float zr_ = acc[mi][ni][1] + bR;
                float sv = zl * (1.0f/(1.0f + expf(-zr_))) + g_x[(size_t)mg*HH + oc];
                g_s[(size_t)mg*HH + oc] = sv;
            }
            {
                int mg2 = mg + 8;
                float zl = acc[mi][ni][2] + bL;
                float zr_ = acc[mi][ni][3] + bR;
                float sv = zl * (1.0f/(1.0f + expf(-zr_))) + g_x[(size_t)mg2*HH + oc];
                g_s[(size_t)mg2*HH + oc] = sv;
            }
        }
    }
}

// ---------------------------------------------------------------------------
// LayerNorm warp-per-row + fused heads on last layer
// ---------------------------------------------------------------------------
__device__ __forceinline__ float softplus_f(float x) {
    return fmaxf(x, 0.f) + log1pf(expf(-fabsf(x)));
}

__global__ void __launch_bounds__(256) ln_kernel(
    const float* __restrict__ lng, const float* __restrict__ lnb,
    const float* __restrict__ mu_w, const float* __restrict__ mu_b,
    const float* __restrict__ al_w, const float* __restrict__ al_b,
    float* __restrict__ out, int half, int do_head)
{
    const int w = threadIdx.x >> 5, lane = threadIdx.x & 31;
    const int row = blockIdx.x*8 + w;
    const float4* sp = (const float4*)(g_s + (size_t)row*HH);
    float4 v0 = sp[lane];
    float4 v1 = sp[lane + 32];

    float s1 = v0.x+v0.y+v0.z+v0.w + v1.x+v1.y+v1.z+v1.w;
    float s2 = v0.x*v0.x+v0.y*v0.y+v0.z*v0.z+v0.w*v0.w
             + v1.x*v1.x+v1.y*v1.y+v1.z*v1.z+v1.w*v1.w;
    #pragma unroll
    for (int o = 16; o > 0; o >>= 1) {
        s1 += __shfl_xor_sync(0xffffffffu, s1, o);
        s2 += __shfl_xor_sync(0xffffffffu, s2, o);
    }
    float mean = s1 * (1.0f/HH);
    float var  = s2 * (1.0f/HH) - mean*mean;
    float inv  = rsqrtf(var + 1e-5f);

    const float4* gp = (const float4*)lng;
    const float4* bp = (const float4*)lnb;
    float4 g0 = gp[lane], g1 = gp[lane+32];
    float4 b0 = bp[lane], b1 = bp[lane+32];
    float4 y0, y1;
    y0.x = (v0.x-mean)*inv*g0.x + b0.x;  y0.y = (v0.y-mean)*inv*g0.y + b0.y;
    y0.z = (v0.z-mean)*inv*g0.z + b0.z;  y0.w = (v0.w-mean)*inv*g0.w + b0.w;
    y1.x = (v1.x-mean)*inv*g1.x + b1.x;  y1.y = (v1.y-mean)*inv*g1.y + b1.y;
    y1.z = (v1.z-mean)*inv*g1.z + b1.z;  y1.w = (v1.w-mean)*inv*g1.w + b1.w;

    float4* xp = (float4*)(g_x + (size_t)row*HH);
    xp[lane] = y0;
    xp[lane + 32] = y1;

    if (do_head) {
        const float4* mp = (const float4*)mu_w;
        const float4* ap = (const float4*)al_w;
        float4 m0 = mp[lane], m1 = mp[lane+32];
        float4 a0 = ap[lane], a1 = ap[lane+32];
        float sm = y0.x*m0.x + y0.y*m0.y + y0.z*m0.z + y0.w*m0.w
                 + y1.x*m1.x + y1.y*m1.y + y1.z*m1.z + y1.w*m1.w;
        float sa = y0.x*a0.x + y0.y*a0.y + y0.z*a0.z + y0.w*a0.w
                 + y1.x*a1.x + y1.y*a1.y + y1.z*a1.z + y1.w*a1.w;
        #pragma unroll
        for (int o = 16; o > 0; o >>= 1) {
            sm += __shfl_xor_sync(0xffffffffu, sm, o);
            sa += __shfl_xor_sync(0xffffffffu, sa, o);
        }
        if (lane == 0) {
            out[row]        = softplus_f(sm + mu_b[0]);
            out[half + row] = softplus_f(sa + al_b[0]);
        }
    }
}

// ---------------------------------------------------------------------------
extern "C" void kernel_launch(void* const* d_in, const int* in_sizes, int n_in,
                              void* d_out, int out_size)
{
    const float* x      = (const float*)d_in[0];
    const float* enc_w  = (const float*)d_in[1];
    const float* enc_b  = (const float*)d_in[2];
    const float* log_dt = (const float*)d_in[3];
    const float* logA   = (const float*)d_in[4];
    const float* A_im   = (const float*)d_in[5];
    const float* C_re   = (const float*)d_in[6];
    const float* C_im   = (const float*)d_in[7];
    const float* Dp     = (const float*)d_in[8];
    const float* out_w  = (const float*)d_in[9];
    const float* out_b  = (const float*)d_in[10];
    const float* ln_g   = (const float*)d_in[11];
    const float* ln_b   = (const float*)d_in[12];
    const float* mu_w   = (const float*)d_in[13];
    const float* mu_b   = (const float*)d_in[14];
    const float* al_w   = (const float*)d_in[15];
    const float* al_b   = (const float*)d_in[16];
    float* out = (float*)d_out;

    enc_kernel<<<GM, HH>>>(x, enc_w, enc_b);
    wconv_kernel<<<(NLAYERS*GN*GK)/256, 256>>>(out_w);
    genG_all_kernel<<<dim3(HH, NLAYERS), 128>>>(log_dt, logA, A_im, C_re, C_im, Dp);

    for (int l = 0; l < NLAYERS; l++) {
        const float* ldt = log_dt + l*HH;
        const float* lA  = logA   + (size_t)l*HH*NN;
        const float* Ai  = A_im   + (size_t)l*HH*NN;

        fwdT_kernel<<<dim3(MM, 8), 256>>>();
        gemm_s4_kernel<<<dim3(4, HH), 256>>>(1, l);
        scanfix_kernel<<<(BB*HH*NN)/256, 256>>>(ldt, lA, Ai);
        gemm_s4_kernel<<<dim3(4, HH), 256>>>(2, l);
        backT_kernel<<<dim3(MM/32, TT/8, HH/32), 256>>>();
        gemm_glu_kernel<<<dim3(8, GM/128), 256>>>(l, out_b + (size_t)l*GN);
        ln_kernel<<<GM/8, 256>>>(ln_g + l*HH, ln_b + l*HH,
                                 mu_w, mu_b, al_w, al_b,
                                 out, out_size/2, (l == NLAYERS-1) ? 1 : 0);
    }
}